// round 1
// baseline (speedup 1.0000x reference)
#include <cuda_runtime.h>
#include <cuda_bf16.h>
#include <math.h>

#define NN 50000
#define EE 400000
#define HID 64
#define HEADS 4
#define INDIM 128

// ---------------- scratch (no allocations allowed) ----------------
__device__ int   g_is64;
__device__ int   g_deg[NN];
__device__ int   g_row_ptr[NN + 1];
__device__ int   g_cursor[NN];
__device__ int   g_csr[EE + NN];
__device__ float g_dinv[NN];
__device__ __align__(16) float g_xw[NN * HID];
__device__ __align__(16) float g_h1[NN * HID];
__device__ __align__(16) float g_z[NN * HEADS * HID];
__device__ __align__(16) float g_as[NN * HEADS];
__device__ __align__(16) float g_ad[NN * HEADS];
__device__ __align__(16) float g_h2[NN * HID];

// ---------------- helpers ----------------
__device__ __forceinline__ int load_edge(const void* ei, long long idx) {
    if (g_is64) return (int)((const long long*)ei)[idx];
    return ((const int*)ei)[idx];
}

__device__ __forceinline__ float lrelu(float v) { return fmaxf(v, 0.2f * v); }

// ---------------- dtype detection: int64 vs int32 edge_index ----------------
__global__ void detect_kernel(const int* ei_words) {
    __shared__ int cnt;
    if (threadIdx.x == 0) cnt = 0;
    __syncthreads();
    int c = 0;
    for (int i = threadIdx.x; i < 2048; i += blockDim.x)
        if (ei_words[2 * i + 1] != 0) c++;
    atomicAdd(&cnt, c);
    __syncthreads();
    if (threadIdx.x == 0) g_is64 = (cnt < 100) ? 1 : 0;
}

// ---------------- degree histogram (init to 1 for self-loop) ----------------
__global__ void init_deg_kernel(int n) {
    int i = blockIdx.x * blockDim.x + threadIdx.x;
    if (i < n) g_deg[i] = 1;
}

__global__ void hist_kernel(const void* ei, int E) {
    int i = blockIdx.x * blockDim.x + threadIdx.x;
    if (i >= E) return;
    int d = load_edge(ei, (long long)E + i);
    atomicAdd(&g_deg[d], 1);
}

// ---------------- single-block exclusive scan -> row_ptr, dinv ----------------
__global__ void scan_kernel(int n) {
    __shared__ int wsum[32];
    __shared__ int s_carry;
    int tid = threadIdx.x, lane = tid & 31, wid = tid >> 5;
    if (tid == 0) s_carry = 0;
    __syncthreads();
    for (int base = 0; base < n; base += blockDim.x) {
        int i = base + tid;
        int v = (i < n) ? g_deg[i] : 0;
        int x = v;
#pragma unroll
        for (int off = 1; off < 32; off <<= 1) {
            int y = __shfl_up_sync(0xffffffffu, x, off);
            if (lane >= off) x += y;
        }
        if (lane == 31) wsum[wid] = x;
        __syncthreads();
        if (wid == 0) {
            int t = wsum[lane];
#pragma unroll
            for (int off = 1; off < 32; off <<= 1) {
                int y = __shfl_up_sync(0xffffffffu, t, off);
                if (lane >= off) t += y;
            }
            wsum[lane] = t;
        }
        __syncthreads();
        int warp_excl = (wid > 0) ? wsum[wid - 1] : 0;
        int incl = x + warp_excl + s_carry;
        if (i < n) {
            g_row_ptr[i] = incl - v;
            g_dinv[i] = rsqrtf((float)v);   // deg >= 1 always (self-loop)
        }
        __syncthreads();
        if (tid == blockDim.x - 1) s_carry = incl;
        __syncthreads();
    }
    if (threadIdx.x == 0) g_row_ptr[n] = s_carry;
}

__global__ void init_cursor_kernel(int n) {
    int i = blockIdx.x * blockDim.x + threadIdx.x;
    if (i < n) g_cursor[i] = g_row_ptr[i];
}

// ---------------- CSR fill (edges + self-loops) ----------------
__global__ void fill_csr_kernel(const void* ei, int E, int n) {
    int i = blockIdx.x * blockDim.x + threadIdx.x;
    int total = E + n;
    if (i >= total) return;
    int s, d;
    if (i < E) { s = load_edge(ei, i); d = load_edge(ei, (long long)E + i); }
    else { s = d = i - E; }
    int pos = atomicAdd(&g_cursor[d], 1);
    g_csr[pos] = s;
}

// ---------------- GEMM1: xw = x @ W_gcn   [N,128]@[128,64] ----------------
__global__ void gemm1_kernel(const float* __restrict__ x, const float* __restrict__ W, int n) {
    __shared__ float Ws[INDIM * HID];   // 32 KB
    __shared__ float xs[8 * INDIM];     // 4 KB
    int tid = threadIdx.x, wid = tid >> 5, lane = tid & 31;
    for (int i = tid; i < INDIM * HID; i += 256) Ws[i] = W[i];
    int row = blockIdx.x * 8 + wid;
    if (row < n) {
#pragma unroll
        for (int q = 0; q < 4; q++) xs[wid * INDIM + lane + q * 32] = x[row * INDIM + lane + q * 32];
    }
    __syncthreads();
    if (row >= n) return;
    float a0 = 0.f, a1 = 0.f;
#pragma unroll 8
    for (int k = 0; k < INDIM; k++) {
        float xv = xs[wid * INDIM + k];
        a0 += xv * Ws[k * HID + lane];
        a1 += xv * Ws[k * HID + 32 + lane];
    }
    g_xw[row * HID + lane] = a0;
    g_xw[row * HID + 32 + lane] = a1;
}

// ---------------- GCN aggregate: h1 = relu(sum norm*xw[src] + b) ----------------
__global__ void gcn_agg_kernel(const float* __restrict__ b_gcn, int n) {
    int node = (blockIdx.x * blockDim.x + threadIdx.x) >> 5;
    int lane = threadIdx.x & 31;
    if (node >= n) return;
    int start = g_row_ptr[node], end = g_row_ptr[node + 1];
    float dn = g_dinv[node];
    float a0 = 0.f, a1 = 0.f;
    for (int e = start; e < end; e++) {
        int s = g_csr[e];
        float w = g_dinv[s] * dn;
        a0 += w * g_xw[s * HID + lane];
        a1 += w * g_xw[s * HID + 32 + lane];
    }
    g_h1[node * HID + lane]      = fmaxf(a0 + b_gcn[lane], 0.f);
    g_h1[node * HID + 32 + lane] = fmaxf(a1 + b_gcn[lane + 32], 0.f);
}

// ---------------- GEMM2: z = h1 @ W_gat   [N,64]@[64,256] ----------------
__global__ void gemm2_kernel(const float* __restrict__ Wg, int n) {
    __shared__ float hs[8 * HID];
    int tid = threadIdx.x, wid = tid >> 5, lane = tid & 31;
    int row = blockIdx.x * 8 + wid;
    if (row < n) {
        hs[wid * HID + lane]      = g_h1[row * HID + lane];
        hs[wid * HID + 32 + lane] = g_h1[row * HID + 32 + lane];
    }
    __syncthreads();
    if (row >= n) return;
    float4 ac0 = make_float4(0.f, 0.f, 0.f, 0.f);
    float4 ac1 = make_float4(0.f, 0.f, 0.f, 0.f);
#pragma unroll 4
    for (int k = 0; k < HID; k++) {
        float hv = hs[wid * HID + k];
        const float4* wr = (const float4*)(Wg + k * 256);
        float4 wa = wr[lane];
        float4 wb = wr[lane + 32];
        ac0.x += hv * wa.x; ac0.y += hv * wa.y; ac0.z += hv * wa.z; ac0.w += hv * wa.w;
        ac1.x += hv * wb.x; ac1.y += hv * wb.y; ac1.z += hv * wb.z; ac1.w += hv * wb.w;
    }
    ((float4*)(g_z + row * 256))[lane]      = ac0;
    ((float4*)(g_z + row * 256))[lane + 32] = ac1;
}

// ---------------- attention dots: a_s, a_d ----------------
__global__ void attn_dot_kernel(const float* __restrict__ att_src,
                                const float* __restrict__ att_dst, int n) {
    int node = (blockIdx.x * blockDim.x + threadIdx.x) >> 5;
    int lane = threadIdx.x & 31;
    if (node >= n) return;
    const float* zr = g_z + node * 256;
#pragma unroll
    for (int h = 0; h < HEADS; h++) {
        float v0 = zr[h * HID + lane], v1 = zr[h * HID + 32 + lane];
        float ss = v0 * att_src[h * HID + lane] + v1 * att_src[h * HID + 32 + lane];
        float sd = v0 * att_dst[h * HID + lane] + v1 * att_dst[h * HID + 32 + lane];
#pragma unroll
        for (int off = 16; off; off >>= 1) {
            ss += __shfl_xor_sync(0xffffffffu, ss, off);
            sd += __shfl_xor_sync(0xffffffffu, sd, off);
        }
        if (lane == 0) { g_as[node * HEADS + h] = ss; g_ad[node * HEADS + h] = sd; }
    }
}

// ---------------- GAT aggregate with segment softmax ----------------
__global__ void gat_agg_kernel(const float* __restrict__ b_gat, int n) {
    int node = (blockIdx.x * blockDim.x + threadIdx.x) >> 5;
    int lane = threadIdx.x & 31;
    if (node >= n) return;
    int start = g_row_ptr[node], end = g_row_ptr[node + 1];
    float4 ad = ((const float4*)g_ad)[node];

    // pass 1: per-head max over incoming edges
    float m0 = -1e30f, m1 = -1e30f, m2 = -1e30f, m3 = -1e30f;
    for (int e = start + lane; e < end; e += 32) {
        int s = g_csr[e];
        float4 as = ((const float4*)g_as)[s];
        m0 = fmaxf(m0, lrelu(as.x + ad.x));
        m1 = fmaxf(m1, lrelu(as.y + ad.y));
        m2 = fmaxf(m2, lrelu(as.z + ad.z));
        m3 = fmaxf(m3, lrelu(as.w + ad.w));
    }
#pragma unroll
    for (int off = 16; off; off >>= 1) {
        m0 = fmaxf(m0, __shfl_xor_sync(0xffffffffu, m0, off));
        m1 = fmaxf(m1, __shfl_xor_sync(0xffffffffu, m1, off));
        m2 = fmaxf(m2, __shfl_xor_sync(0xffffffffu, m2, off));
        m3 = fmaxf(m3, __shfl_xor_sync(0xffffffffu, m3, off));
    }

    // pass 2: denominators
    float d0 = 0.f, d1 = 0.f, d2 = 0.f, d3 = 0.f;
    for (int e = start + lane; e < end; e += 32) {
        int s = g_csr[e];
        float4 as = ((const float4*)g_as)[s];
        d0 += __expf(lrelu(as.x + ad.x) - m0);
        d1 += __expf(lrelu(as.y + ad.y) - m1);
        d2 += __expf(lrelu(as.z + ad.z) - m2);
        d3 += __expf(lrelu(as.w + ad.w) - m3);
    }
#pragma unroll
    for (int off = 16; off; off >>= 1) {
        d0 += __shfl_xor_sync(0xffffffffu, d0, off);
        d1 += __shfl_xor_sync(0xffffffffu, d1, off);
        d2 += __shfl_xor_sync(0xffffffffu, d2, off);
        d3 += __shfl_xor_sync(0xffffffffu, d3, off);
    }
    float r0 = 1.f / d0, r1 = 1.f / d1, r2 = 1.f / d2, r3 = 1.f / d3;

    // pass 3: cooperative weighted aggregation of z[src]
    float acc[8];
#pragma unroll
    for (int i = 0; i < 8; i++) acc[i] = 0.f;
    for (int e = start; e < end; e++) {
        int s = g_csr[e];
        float4 as = ((const float4*)g_as)[s];
        float al0 = __expf(lrelu(as.x + ad.x) - m0) * r0;
        float al1 = __expf(lrelu(as.y + ad.y) - m1) * r1;
        float al2 = __expf(lrelu(as.z + ad.z) - m2) * r2;
        float al3 = __expf(lrelu(as.w + ad.w) - m3) * r3;
        const float* zp = g_z + (long long)s * 256;
        acc[0] += al0 * zp[lane];        acc[1] += al0 * zp[32 + lane];
        acc[2] += al1 * zp[64 + lane];   acc[3] += al1 * zp[96 + lane];
        acc[4] += al2 * zp[128 + lane];  acc[5] += al2 * zp[160 + lane];
        acc[6] += al3 * zp[192 + lane];  acc[7] += al3 * zp[224 + lane];
    }
    float o0 = 0.25f * (acc[0] + acc[2] + acc[4] + acc[6]);
    float o1 = 0.25f * (acc[1] + acc[3] + acc[5] + acc[7]);
    g_h2[node * HID + lane]      = fmaxf(o0 + b_gat[lane], 0.f);
    g_h2[node * HID + 32 + lane] = fmaxf(o1 + b_gat[lane + 32], 0.f);
}

// ---------------- final: patch GEMM + residual + LayerNorm ----------------
__global__ void final_kernel(const float* __restrict__ Wp, const float* __restrict__ b_patch,
                             const float* __restrict__ gamma, const float* __restrict__ beta,
                             float* __restrict__ out, int n) {
    __shared__ float Ws[HID * HID];   // 16 KB
    __shared__ float hs[8 * HID];
    int tid = threadIdx.x, wid = tid >> 5, lane = tid & 31;
    for (int i = tid; i < HID * HID; i += 256) Ws[i] = Wp[i];
    int row = blockIdx.x * 8 + wid;
    float v0 = 0.f, v1 = 0.f;
    if (row < n) {
        v0 = g_h1[row * HID + lane];
        v1 = g_h1[row * HID + 32 + lane];
        hs[wid * HID + lane] = v0;
        hs[wid * HID + 32 + lane] = v1;
    }
    __syncthreads();
    if (row >= n) return;
    float p0 = 0.f, p1 = 0.f;
#pragma unroll 8
    for (int k = 0; k < HID; k++) {
        float hv = hs[wid * HID + k];
        p0 += hv * Ws[k * HID + lane];
        p1 += hv * Ws[k * HID + 32 + lane];
    }
    float hA = v0 + g_h2[row * HID + lane]      + p0 + b_patch[lane];
    float hB = v1 + g_h2[row * HID + 32 + lane] + p1 + b_patch[lane + 32];
    float s = hA + hB, sq = hA * hA + hB * hB;
#pragma unroll
    for (int off = 16; off; off >>= 1) {
        s  += __shfl_xor_sync(0xffffffffu, s, off);
        sq += __shfl_xor_sync(0xffffffffu, sq, off);
    }
    float mu = s * (1.f / 64.f);
    float var = sq * (1.f / 64.f) - mu * mu;
    float rstd = rsqrtf(var + 1e-5f);
    out[row * HID + lane]      = (hA - mu) * rstd * gamma[lane] + beta[lane];
    out[row * HID + 32 + lane] = (hB - mu) * rstd * gamma[lane + 32] + beta[lane + 32];
}

// ---------------- launch ----------------
extern "C" void kernel_launch(void* const* d_in, const int* in_sizes, int n_in,
                              void* d_out, int out_size) {
    const float* x        = (const float*)d_in[0];
    const void*  ei       = d_in[1];
    const float* W_gcn    = (const float*)d_in[2];
    const float* b_gcn    = (const float*)d_in[3];
    const float* W_gat    = (const float*)d_in[4];
    const float* att_src  = (const float*)d_in[5];
    const float* att_dst  = (const float*)d_in[6];
    const float* b_gat    = (const float*)d_in[7];
    const float* W_patch  = (const float*)d_in[8];
    const float* b_patch  = (const float*)d_in[9];
    const float* gamma    = (const float*)d_in[10];
    const float* beta     = (const float*)d_in[11];
    float* out = (float*)d_out;

    int n = in_sizes[0] / INDIM;          // 50000
    int E = in_sizes[1] / 2;              // 400000

    const int T = 256;
    int gN   = (n + T - 1) / T;
    int gE   = (E + T - 1) / T;
    int gEN  = (E + n + T - 1) / T;
    int gRow = (n + 7) / 8;               // 8 warp-rows per block
    int gWpN = (n * 32 + T - 1) / T;      // warp-per-node

    detect_kernel<<<1, 256>>>((const int*)ei);
    init_deg_kernel<<<gN, T>>>(n);
    hist_kernel<<<gE, T>>>(ei, E);
    scan_kernel<<<1, 1024>>>(n);
    init_cursor_kernel<<<gN, T>>>(n);
    fill_csr_kernel<<<gEN, T>>>(ei, E, n);
    gemm1_kernel<<<gRow, T>>>(x, W_gcn, n);
    gcn_agg_kernel<<<gWpN, T>>>(b_gcn, n);
    gemm2_kernel<<<gRow, T>>>(W_gat, n);
    attn_dot_kernel<<<gWpN, T>>>(att_src, att_dst, n);
    gat_agg_kernel<<<gWpN, T>>>(b_gat, n);
    final_kernel<<<gRow, T>>>(W_patch, b_patch, gamma, beta, out, n);
}

// round 2
// speedup vs baseline: 1.6765x; 1.6765x over previous
#include <cuda_runtime.h>
#include <cuda_bf16.h>
#include <math.h>

#define NN 50000
#define EE 400000
#define HID 64
#define HEADS 4
#define INDIM 128

// ---------------- scratch (no allocations allowed) ----------------
__device__ int   g_is64;
__device__ int   g_deg[NN];
__device__ int   g_row_ptr[NN + 1];
__device__ int   g_cursor[NN];
__device__ int   g_csr[EE + NN];
__device__ int   g_bsum[1024];
__device__ float g_dinv[NN];
__device__ __align__(16) float g_xw[NN * HID];
__device__ __align__(16) float g_h1[NN * HID];
__device__ __align__(16) float g_z[NN * HEADS * HID];
__device__ __align__(16) float g_as[NN * HEADS];
__device__ __align__(16) float g_ad[NN * HEADS];
__device__ __align__(16) float g_h2[NN * HID];

// ---------------- helpers ----------------
__device__ __forceinline__ int load_edge(const void* ei, long long idx) {
    if (g_is64) return (int)((const long long*)ei)[idx];
    return ((const int*)ei)[idx];
}
__device__ __forceinline__ float lrelu(float v) { return fmaxf(v, 0.2f * v); }

// ---------------- dtype detection: int64 vs int32 edge_index ----------------
__global__ void detect_kernel(const int* ei_words) {
    __shared__ int cnt;
    if (threadIdx.x == 0) cnt = 0;
    __syncthreads();
    int c = 0;
    for (int i = threadIdx.x; i < 2048; i += blockDim.x)
        if (ei_words[2 * i + 1] != 0) c++;
    atomicAdd(&cnt, c);
    __syncthreads();
    if (threadIdx.x == 0) g_is64 = (cnt < 100) ? 1 : 0;
}

// ---------------- degree histogram ----------------
__global__ void init_deg_kernel(int n) {
    int i = blockIdx.x * blockDim.x + threadIdx.x;
    if (i < n) g_deg[i] = 1;
}
__global__ void hist_kernel(const void* ei, int E) {
    int i = blockIdx.x * blockDim.x + threadIdx.x;
    if (i >= E) return;
    int d = load_edge(ei, (long long)E + i);
    atomicAdd(&g_deg[d], 1);
}

// ---------------- decoupled 3-phase scan ----------------
// Phase A: per-256-block exclusive scan; block total -> g_bsum; also dinv.
__global__ void scanA_kernel(int n) {
    __shared__ int wsum[8];
    int t = threadIdx.x, lane = t & 31, wid = t >> 5;
    int i = blockIdx.x * 256 + t;
    int v = (i < n) ? g_deg[i] : 0;
    int x = v;
#pragma unroll
    for (int off = 1; off < 32; off <<= 1) {
        int y = __shfl_up_sync(0xffffffffu, x, off);
        if (lane >= off) x += y;
    }
    if (lane == 31) wsum[wid] = x;
    __syncthreads();
    if (wid == 0) {
        int y = (lane < 8) ? wsum[lane] : 0;
#pragma unroll
        for (int off = 1; off < 8; off <<= 1) {
            int z = __shfl_up_sync(0xffffffffu, y, off);
            if (lane >= off) y += z;
        }
        if (lane < 8) wsum[lane] = y;
    }
    __syncthreads();
    int excl_w = wid ? wsum[wid - 1] : 0;
    int incl = x + excl_w;
    if (i < n) {
        g_row_ptr[i] = incl - v;
        g_dinv[i] = rsqrtf((float)v);
    }
    if (t == 255) g_bsum[blockIdx.x] = incl;
}

// Phase B: single 1024-thread block exclusive-scans block sums (nb <= 1024).
__global__ void scanB_kernel(int nb, int n, int total) {
    __shared__ int wsum[32];
    int t = threadIdx.x, lane = t & 31, wid = t >> 5;
    int v = (t < nb) ? g_bsum[t] : 0;
    int x = v;
#pragma unroll
    for (int off = 1; off < 32; off <<= 1) {
        int y = __shfl_up_sync(0xffffffffu, x, off);
        if (lane >= off) x += y;
    }
    if (lane == 31) wsum[wid] = x;
    __syncthreads();
    if (wid == 0) {
        int y = wsum[lane];
#pragma unroll
        for (int off = 1; off < 32; off <<= 1) {
            int z = __shfl_up_sync(0xffffffffu, y, off);
            if (lane >= off) y += z;
        }
        wsum[lane] = y;
    }
    __syncthreads();
    int excl_w = wid ? wsum[wid - 1] : 0;
    if (t < nb) g_bsum[t] = x + excl_w - v;   // exclusive
    if (t == 0) g_row_ptr[n] = total;
}

// Phase C: add block offsets; init cursor.
__global__ void scanC_kernel(int n) {
    int i = blockIdx.x * blockDim.x + threadIdx.x;
    if (i >= n) return;
    int rp = g_row_ptr[i] + g_bsum[i >> 8];
    g_row_ptr[i] = rp;
    g_cursor[i] = rp;
}

// ---------------- CSR fill (edges + self-loops) ----------------
__global__ void fill_csr_kernel(const void* ei, int E, int n) {
    int i = blockIdx.x * blockDim.x + threadIdx.x;
    int total = E + n;
    if (i >= total) return;
    int s, d;
    if (i < E) { s = load_edge(ei, i); d = load_edge(ei, (long long)E + i); }
    else { s = d = i - E; }
    int pos = atomicAdd(&g_cursor[d], 1);
    g_csr[pos] = s;
}

// ---------------- GEMM1 (tiled): xw = x @ W_gcn   [N,128]@[128,64] ----------------
// Block: 128 rows x 64 cols. Thread: 4 cols x 8 rows. K chunked by 32.
__global__ void gemm1_kernel(const float* __restrict__ x, const float* __restrict__ W, int n) {
    __shared__ float Ws[INDIM * HID];   // 32 KB
    __shared__ float xs[128 * 32];      // 16 KB
    int tid = threadIdx.x, q = tid & 15, rg = tid >> 4;
    for (int i = tid; i < INDIM * HID; i += 256) Ws[i] = W[i];
    int rowbase = blockIdx.x * 128;
    float4 acc[8];
#pragma unroll
    for (int j = 0; j < 8; j++) acc[j] = make_float4(0.f, 0.f, 0.f, 0.f);
    const float4* x4 = (const float4*)x;
    float4* xs4 = (float4*)xs;
    const float4* Ws4 = (const float4*)Ws;
    for (int ch = 0; ch < 4; ch++) {
        __syncthreads();
        for (int l = tid; l < 1024; l += 256) {
            int r = l >> 3, c4 = l & 7;
            int row = rowbase + r;
            float4 v = make_float4(0.f, 0.f, 0.f, 0.f);
            if (row < n) v = x4[row * 32 + ch * 8 + c4];
            xs4[r * 8 + c4] = v;
        }
        __syncthreads();
#pragma unroll 4
        for (int kk = 0; kk < 32; kk++) {
            float4 w = Ws4[(ch * 32 + kk) * 16 + q];
#pragma unroll
            for (int j = 0; j < 8; j++) {
                float xv = xs[(rg * 8 + j) * 32 + kk];
                acc[j].x += xv * w.x; acc[j].y += xv * w.y;
                acc[j].z += xv * w.z; acc[j].w += xv * w.w;
            }
        }
    }
    float4* xw4 = (float4*)g_xw;
#pragma unroll
    for (int j = 0; j < 8; j++) {
        int row = rowbase + rg * 8 + j;
        if (row < n) xw4[row * 16 + q] = acc[j];
    }
}

// ---------------- GCN aggregate ----------------
__global__ void gcn_agg_kernel(const float* __restrict__ b_gcn, int n) {
    int node = (blockIdx.x * blockDim.x + threadIdx.x) >> 5;
    int lane = threadIdx.x & 31;
    if (node >= n) return;
    int start = g_row_ptr[node], end = g_row_ptr[node + 1];
    float dn = g_dinv[node];
    const float2* xw2 = (const float2*)g_xw;
    float2 acc = make_float2(0.f, 0.f);
    for (int e = start; e < end; e++) {
        int s = g_csr[e];
        float w = g_dinv[s] * dn;
        float2 v = xw2[s * 32 + lane];
        acc.x += w * v.x; acc.y += w * v.y;
    }
    float2 b = ((const float2*)b_gcn)[lane];
    float2 o;
    o.x = fmaxf(acc.x + b.x, 0.f);
    o.y = fmaxf(acc.y + b.y, 0.f);
    ((float2*)g_h1)[node * 32 + lane] = o;
}

// ---------------- GEMM2 (tiled) + fused attention dots ----------------
// Block: 32 rows x 256 cols. Thread: 4 cols x 8 rows. W streamed from L1.
__global__ void gemm2_kernel(const float* __restrict__ Wg,
                             const float* __restrict__ att_src,
                             const float* __restrict__ att_dst, int n) {
    __shared__ float hs[32 * HID];   // 8 KB
    int tid = threadIdx.x, q = tid & 63, rg = tid >> 6, lane = tid & 31;
    int rowbase = blockIdx.x * 32;
    const float4* h1_4 = (const float4*)g_h1;
    float4* hs4 = (float4*)hs;
    for (int l = tid; l < 512; l += 256) {
        int r = l >> 4, c4 = l & 15;
        int row = rowbase + r;
        hs4[l] = (row < n) ? h1_4[row * 16 + c4] : make_float4(0.f, 0.f, 0.f, 0.f);
    }
    __syncthreads();
    float4 acc[8];
#pragma unroll
    for (int j = 0; j < 8; j++) acc[j] = make_float4(0.f, 0.f, 0.f, 0.f);
    const float4* Wg4 = (const float4*)Wg;
#pragma unroll 4
    for (int k = 0; k < HID; k++) {
        float4 w = Wg4[k * 64 + q];
#pragma unroll
        for (int j = 0; j < 8; j++) {
            float hv = hs[(rg * 8 + j) * HID + k];
            acc[j].x += hv * w.x; acc[j].y += hv * w.y;
            acc[j].z += hv * w.z; acc[j].w += hv * w.w;
        }
    }
    float4* z4 = (float4*)g_z;
    float4 asq = ((const float4*)att_src)[q];
    float4 adq = ((const float4*)att_dst)[q];
    float ps[8], pd[8];
#pragma unroll
    for (int j = 0; j < 8; j++) {
        int row = rowbase + rg * 8 + j;
        if (row < n) z4[row * 64 + q] = acc[j];
        ps[j] = acc[j].x * asq.x + acc[j].y * asq.y + acc[j].z * asq.z + acc[j].w * asq.w;
        pd[j] = acc[j].x * adq.x + acc[j].y * adq.y + acc[j].z * adq.z + acc[j].w * adq.w;
    }
#pragma unroll
    for (int off = 8; off; off >>= 1) {
#pragma unroll
        for (int j = 0; j < 8; j++) {
            ps[j] += __shfl_xor_sync(0xffffffffu, ps[j], off);
            pd[j] += __shfl_xor_sync(0xffffffffu, pd[j], off);
        }
    }
    int head = q >> 4;
    if ((lane & 15) == 0) {
#pragma unroll
        for (int j = 0; j < 8; j++) {
            int row = rowbase + rg * 8 + j;
            if (row < n) { g_as[row * 4 + head] = ps[j]; g_ad[row * 4 + head] = pd[j]; }
        }
    }
}

// ---------------- GAT aggregate: max pass, then single fused exp/agg pass ----------------
__global__ void gat_agg_kernel(const float* __restrict__ b_gat, int n) {
    int node = (blockIdx.x * blockDim.x + threadIdx.x) >> 5;
    int lane = threadIdx.x & 31;
    if (node >= n) return;
    int start = g_row_ptr[node], end = g_row_ptr[node + 1];
    const float4* as4 = (const float4*)g_as;
    float4 ad = ((const float4*)g_ad)[node];

    // pass 1: per-head max (lane-parallel)
    float m0 = -1e30f, m1 = -1e30f, m2 = -1e30f, m3 = -1e30f;
    for (int e = start + lane; e < end; e += 32) {
        int s = g_csr[e];
        float4 a = as4[s];
        m0 = fmaxf(m0, lrelu(a.x + ad.x));
        m1 = fmaxf(m1, lrelu(a.y + ad.y));
        m2 = fmaxf(m2, lrelu(a.z + ad.z));
        m3 = fmaxf(m3, lrelu(a.w + ad.w));
    }
#pragma unroll
    for (int off = 16; off; off >>= 1) {
        m0 = fmaxf(m0, __shfl_xor_sync(0xffffffffu, m0, off));
        m1 = fmaxf(m1, __shfl_xor_sync(0xffffffffu, m1, off));
        m2 = fmaxf(m2, __shfl_xor_sync(0xffffffffu, m2, off));
        m3 = fmaxf(m3, __shfl_xor_sync(0xffffffffu, m3, off));
    }

    // pass 2 (fused): accumulate unnormalized ex*z and ex sums; normalize at end
    const float4* z4 = (const float4*)g_z;
    float4 accA = make_float4(0.f, 0.f, 0.f, 0.f);
    float4 accB = make_float4(0.f, 0.f, 0.f, 0.f);
    float d0 = 0.f, d1 = 0.f, d2 = 0.f, d3 = 0.f;
    for (int e = start; e < end; e++) {
        int s = g_csr[e];
        float4 a = as4[s];
        float e0 = __expf(lrelu(a.x + ad.x) - m0);
        float e1 = __expf(lrelu(a.y + ad.y) - m1);
        float e2 = __expf(lrelu(a.z + ad.z) - m2);
        float e3 = __expf(lrelu(a.w + ad.w) - m3);
        d0 += e0; d1 += e1; d2 += e2; d3 += e3;
        float4 za = z4[s * 64 + lane];        // heads 0/1 (lane<16 : h0 else h1)
        float4 zb = z4[s * 64 + 32 + lane];   // heads 2/3
        float eA = (lane < 16) ? e0 : e1;
        float eB = (lane < 16) ? e2 : e3;
        accA.x += eA * za.x; accA.y += eA * za.y; accA.z += eA * za.z; accA.w += eA * za.w;
        accB.x += eB * zb.x; accB.y += eB * zb.y; accB.z += eB * zb.z; accB.w += eB * zb.w;
    }
    float rA = (lane < 16) ? (1.f / d0) : (1.f / d1);
    float rB = (lane < 16) ? (1.f / d2) : (1.f / d3);
    float4 s4;
    s4.x = accA.x * rA + accB.x * rB;
    s4.y = accA.y * rA + accB.y * rB;
    s4.z = accA.z * rA + accB.z * rB;
    s4.w = accA.w * rA + accB.w * rB;
    s4.x += __shfl_xor_sync(0xffffffffu, s4.x, 16);
    s4.y += __shfl_xor_sync(0xffffffffu, s4.y, 16);
    s4.z += __shfl_xor_sync(0xffffffffu, s4.z, 16);
    s4.w += __shfl_xor_sync(0xffffffffu, s4.w, 16);
    int c = lane & 15;
    float4 b = ((const float4*)b_gat)[c];
    float4 o;
    o.x = fmaxf(0.25f * s4.x + b.x, 0.f);
    o.y = fmaxf(0.25f * s4.y + b.y, 0.f);
    o.z = fmaxf(0.25f * s4.z + b.z, 0.f);
    o.w = fmaxf(0.25f * s4.w + b.w, 0.f);
    if (lane < 16) ((float4*)g_h2)[node * 16 + c] = o;
}

// ---------------- final (tiled): patch GEMM + residual + LayerNorm ----------------
// Block: 128 rows x 64 cols. Thread: 4 cols x 8 rows.
__global__ void final_kernel(const float* __restrict__ Wp, const float* __restrict__ b_patch,
                             const float* __restrict__ gamma, const float* __restrict__ beta,
                             float* __restrict__ out, int n) {
    __shared__ float Ws[HID * HID];    // 16 KB
    __shared__ float hs[128 * HID];    // 32 KB
    int tid = threadIdx.x, q = tid & 15, rg = tid >> 4;
    for (int i = tid; i < HID * HID; i += 256) Ws[i] = Wp[i];
    int rowbase = blockIdx.x * 128;
    const float4* h1_4 = (const float4*)g_h1;
    float4* hs4 = (float4*)hs;
    for (int l = tid; l < 2048; l += 256) {
        int r = l >> 4, c4 = l & 15;
        int row = rowbase + r;
        hs4[l] = (row < n) ? h1_4[row * 16 + c4] : make_float4(0.f, 0.f, 0.f, 0.f);
    }
    __syncthreads();
    float4 acc[8];
#pragma unroll
    for (int j = 0; j < 8; j++) acc[j] = make_float4(0.f, 0.f, 0.f, 0.f);
    const float4* Ws4 = (const float4*)Ws;
#pragma unroll 4
    for (int k = 0; k < HID; k++) {
        float4 w = Ws4[k * 16 + q];
#pragma unroll
        for (int j = 0; j < 8; j++) {
            float hv = hs[(rg * 8 + j) * HID + k];
            acc[j].x += hv * w.x; acc[j].y += hv * w.y;
            acc[j].z += hv * w.z; acc[j].w += hv * w.w;
        }
    }
    const float4* h2_4 = (const float4*)g_h2;
    float4 bp  = ((const float4*)b_patch)[q];
    float4 g4  = ((const float4*)gamma)[q];
    float4 bt4 = ((const float4*)beta)[q];
    float4* out4 = (float4*)out;
#pragma unroll
    for (int j = 0; j < 8; j++) {
        int row = rowbase + rg * 8 + j;
        float4 h1v = hs4[(rg * 8 + j) * 16 + q];
        float4 h2v = (row < n) ? h2_4[row * 16 + q] : make_float4(0.f, 0.f, 0.f, 0.f);
        float4 h;
        h.x = h1v.x + h2v.x + acc[j].x + bp.x;
        h.y = h1v.y + h2v.y + acc[j].y + bp.y;
        h.z = h1v.z + h2v.z + acc[j].z + bp.z;
        h.w = h1v.w + h2v.w + acc[j].w + bp.w;
        float s  = h.x + h.y + h.z + h.w;
        float sq = h.x * h.x + h.y * h.y + h.z * h.z + h.w * h.w;
#pragma unroll
        for (int off = 8; off; off >>= 1) {
            s  += __shfl_xor_sync(0xffffffffu, s, off);
            sq += __shfl_xor_sync(0xffffffffu, sq, off);
        }
        float mu = s * (1.f / 64.f);
        float var = sq * (1.f / 64.f) - mu * mu;
        float rstd = rsqrtf(var + 1e-5f);
        if (row < n) {
            float4 o;
            o.x = (h.x - mu) * rstd * g4.x + bt4.x;
            o.y = (h.y - mu) * rstd * g4.y + bt4.y;
            o.z = (h.z - mu) * rstd * g4.z + bt4.z;
            o.w = (h.w - mu) * rstd * g4.w + bt4.w;
            out4[row * 16 + q] = o;
        }
    }
}

// ---------------- launch ----------------
extern "C" void kernel_launch(void* const* d_in, const int* in_sizes, int n_in,
                              void* d_out, int out_size) {
    const float* x        = (const float*)d_in[0];
    const void*  ei       = d_in[1];
    const float* W_gcn    = (const float*)d_in[2];
    const float* b_gcn    = (const float*)d_in[3];
    const float* W_gat    = (const float*)d_in[4];
    const float* att_src  = (const float*)d_in[5];
    const float* att_dst  = (const float*)d_in[6];
    const float* b_gat    = (const float*)d_in[7];
    const float* W_patch  = (const float*)d_in[8];
    const float* b_patch  = (const float*)d_in[9];
    const float* gamma    = (const float*)d_in[10];
    const float* beta     = (const float*)d_in[11];
    float* out = (float*)d_out;

    int n = in_sizes[0] / INDIM;          // 50000
    int E = in_sizes[1] / 2;              // 400000

    const int T = 256;
    int gN   = (n + T - 1) / T;
    int gE   = (E + T - 1) / T;
    int gEN  = (E + n + T - 1) / T;
    int nb   = (n + 255) / 256;
    int g128 = (n + 127) / 128;
    int g32  = (n + 31) / 32;
    int gWpN = (n * 32 + T - 1) / T;      // warp-per-node

    detect_kernel<<<1, 256>>>((const int*)ei);
    init_deg_kernel<<<gN, T>>>(n);
    hist_kernel<<<gE, T>>>(ei, E);
    scanA_kernel<<<nb, 256>>>(n);
    scanB_kernel<<<1, 1024>>>(nb, n, E + n);
    scanC_kernel<<<gN, T>>>(n);
    fill_csr_kernel<<<gEN, T>>>(ei, E, n);
    gemm1_kernel<<<g128, T>>>(x, W_gcn, n);
    gcn_agg_kernel<<<gWpN, T>>>(b_gcn, n);
    gemm2_kernel<<<g32, T>>>(W_gat, att_src, att_dst, n);
    gat_agg_kernel<<<gWpN, T>>>(b_gat, n);
    final_kernel<<<g128, T>>>(W_patch, b_patch, gamma, beta, out, n);
}

// round 3
// speedup vs baseline: 1.8465x; 1.1014x over previous
#include <cuda_runtime.h>
#include <cuda_bf16.h>
#include <math.h>

#define NN 50000
#define EE 400000
#define HID 64
#define HEADS 4
#define INDIM 128

typedef unsigned long long u64;

// ---------------- scratch (no allocations allowed) ----------------
__device__ int   g_is64;
__device__ int   g_deg[NN];
__device__ int   g_row_ptr[NN + 1];
__device__ int   g_cursor[NN];
__device__ int   g_csr[EE + NN];
__device__ int   g_bsum[1024];
__device__ float g_dinv[NN];
__device__ __align__(16) float g_xw[NN * HID];
__device__ __align__(16) float g_h1[NN * HID];
__device__ __align__(16) float g_z[NN * HEADS * HID];
__device__ __align__(16) float g_as[NN * HEADS];
__device__ __align__(16) float g_ad[NN * HEADS];
__device__ __align__(16) float g_h2[NN * HID];

// ---------------- packed f32x2 helpers (SASS FFMA2 path) ----------------
__device__ __forceinline__ u64 pack2(float lo, float hi) {
    u64 r; asm("mov.b64 %0, {%1, %2};" : "=l"(r) : "f"(lo), "f"(hi)); return r;
}
__device__ __forceinline__ void ffma2(u64& d, u64 a, u64 b) {
    asm("fma.rn.f32x2 %0, %1, %2, %0;" : "+l"(d) : "l"(a), "l"(b));
}
__device__ __forceinline__ float2 unpack2(u64 v) {
    float2 f; asm("mov.b64 {%0, %1}, %2;" : "=f"(f.x), "=f"(f.y) : "l"(v)); return f;
}

// ---------------- helpers ----------------
__device__ __forceinline__ int load_edge(const void* ei, long long idx) {
    if (g_is64) return (int)((const long long*)ei)[idx];
    return ((const int*)ei)[idx];
}
__device__ __forceinline__ float lrelu(float v) { return fmaxf(v, 0.2f * v); }

// ---------------- dtype detection: int64 vs int32 edge_index ----------------
__global__ void detect_kernel(const int* ei_words) {
    __shared__ int cnt;
    if (threadIdx.x == 0) cnt = 0;
    __syncthreads();
    int c = 0;
    for (int i = threadIdx.x; i < 2048; i += blockDim.x)
        if (ei_words[2 * i + 1] != 0) c++;
    atomicAdd(&cnt, c);
    __syncthreads();
    if (threadIdx.x == 0) g_is64 = (cnt < 100) ? 1 : 0;
}

// ---------------- degree histogram ----------------
__global__ void init_deg_kernel(int n) {
    int i = blockIdx.x * blockDim.x + threadIdx.x;
    if (i < n) g_deg[i] = 1;
}
__global__ void hist_kernel(const void* ei, int E) {
    int i = blockIdx.x * blockDim.x + threadIdx.x;
    if (i >= E) return;
    int d = load_edge(ei, (long long)E + i);
    atomicAdd(&g_deg[d], 1);
}

// ---------------- decoupled 3-phase scan ----------------
__global__ void scanA_kernel(int n) {
    __shared__ int wsum[8];
    int t = threadIdx.x, lane = t & 31, wid = t >> 5;
    int i = blockIdx.x * 256 + t;
    int v = (i < n) ? g_deg[i] : 0;
    int x = v;
#pragma unroll
    for (int off = 1; off < 32; off <<= 1) {
        int y = __shfl_up_sync(0xffffffffu, x, off);
        if (lane >= off) x += y;
    }
    if (lane == 31) wsum[wid] = x;
    __syncthreads();
    if (wid == 0) {
        int y = (lane < 8) ? wsum[lane] : 0;
#pragma unroll
        for (int off = 1; off < 8; off <<= 1) {
            int z = __shfl_up_sync(0xffffffffu, y, off);
            if (lane >= off) y += z;
        }
        if (lane < 8) wsum[lane] = y;
    }
    __syncthreads();
    int excl_w = wid ? wsum[wid - 1] : 0;
    int incl = x + excl_w;
    if (i < n) {
        g_row_ptr[i] = incl - v;
        g_dinv[i] = rsqrtf((float)v);
    }
    if (t == 255) g_bsum[blockIdx.x] = incl;
}

__global__ void scanB_kernel(int nb, int n, int total) {
    __shared__ int wsum[32];
    int t = threadIdx.x, lane = t & 31, wid = t >> 5;
    int v = (t < nb) ? g_bsum[t] : 0;
    int x = v;
#pragma unroll
    for (int off = 1; off < 32; off <<= 1) {
        int y = __shfl_up_sync(0xffffffffu, x, off);
        if (lane >= off) x += y;
    }
    if (lane == 31) wsum[wid] = x;
    __syncthreads();
    if (wid == 0) {
        int y = wsum[lane];
#pragma unroll
        for (int off = 1; off < 32; off <<= 1) {
            int z = __shfl_up_sync(0xffffffffu, y, off);
            if (lane >= off) y += z;
        }
        wsum[lane] = y;
    }
    __syncthreads();
    int excl_w = wid ? wsum[wid - 1] : 0;
    if (t < nb) g_bsum[t] = x + excl_w - v;
    if (t == 0) g_row_ptr[n] = total;
}

__global__ void scanC_kernel(int n) {
    int i = blockIdx.x * blockDim.x + threadIdx.x;
    if (i >= n) return;
    int rp = g_row_ptr[i] + g_bsum[i >> 8];
    g_row_ptr[i] = rp;
    g_cursor[i] = rp;
}

// ---------------- CSR fill (edges + self-loops) ----------------
__global__ void fill_csr_kernel(const void* ei, int E, int n) {
    int i = blockIdx.x * blockDim.x + threadIdx.x;
    int total = E + n;
    if (i >= total) return;
    int s, d;
    if (i < E) { s = load_edge(ei, i); d = load_edge(ei, (long long)E + i); }
    else { s = d = i - E; }
    int pos = atomicAdd(&g_cursor[d], 1);
    g_csr[pos] = s;
}

// ---------------- GEMM1 (tiled, FFMA2): xw = x @ W_gcn  [N,128]@[128,64] ----------------
__global__ void gemm1_kernel(const float* __restrict__ x, const float* __restrict__ W, int n) {
    __shared__ float Ws[INDIM * HID];   // 32 KB
    __shared__ float xs[128 * 32];      // 16 KB
    int tid = threadIdx.x, q = tid & 15, rg = tid >> 4;
    for (int i = tid; i < INDIM * HID; i += 256) Ws[i] = W[i];
    int rowbase = blockIdx.x * 128;
    u64 accXY[8], accZW[8];
#pragma unroll
    for (int j = 0; j < 8; j++) { accXY[j] = 0ull; accZW[j] = 0ull; }
    const float4* x4 = (const float4*)x;
    float4* xs4 = (float4*)xs;
    const float4* Ws4 = (const float4*)Ws;
    for (int ch = 0; ch < 4; ch++) {
        __syncthreads();
        for (int l = tid; l < 1024; l += 256) {
            int r = l >> 3, c4 = l & 7;
            int row = rowbase + r;
            float4 v = make_float4(0.f, 0.f, 0.f, 0.f);
            if (row < n) v = x4[row * 32 + ch * 8 + c4];
            xs4[r * 8 + c4] = v;
        }
        __syncthreads();
#pragma unroll 4
        for (int kk = 0; kk < 32; kk++) {
            float4 w = Ws4[(ch * 32 + kk) * 16 + q];
            u64 wxy = pack2(w.x, w.y), wzw = pack2(w.z, w.w);
#pragma unroll
            for (int j = 0; j < 8; j++) {
                float xv = xs[(rg * 8 + j) * 32 + kk];
                u64 xv2 = pack2(xv, xv);
                ffma2(accXY[j], xv2, wxy);
                ffma2(accZW[j], xv2, wzw);
            }
        }
    }
    float4* xw4 = (float4*)g_xw;
#pragma unroll
    for (int j = 0; j < 8; j++) {
        int row = rowbase + rg * 8 + j;
        if (row < n) {
            float2 lo = unpack2(accXY[j]), hi = unpack2(accZW[j]);
            xw4[row * 16 + q] = make_float4(lo.x, lo.y, hi.x, hi.y);
        }
    }
}

// ---------------- GCN aggregate ----------------
__global__ void gcn_agg_kernel(const float* __restrict__ b_gcn, int n) {
    int node = (blockIdx.x * blockDim.x + threadIdx.x) >> 5;
    int lane = threadIdx.x & 31;
    if (node >= n) return;
    int start = g_row_ptr[node], end = g_row_ptr[node + 1];
    float dn = g_dinv[node];
    const float2* xw2 = (const float2*)g_xw;
    float2 acc = make_float2(0.f, 0.f);
    int s_next = (start < end) ? g_csr[start] : 0;
    for (int e = start; e < end; e++) {
        int s = s_next;
        if (e + 1 < end) s_next = g_csr[e + 1];
        float w = g_dinv[s] * dn;
        float2 v = xw2[s * 32 + lane];
        acc.x += w * v.x; acc.y += w * v.y;
    }
    float2 b = ((const float2*)b_gcn)[lane];
    float2 o;
    o.x = fmaxf(acc.x + b.x, 0.f);
    o.y = fmaxf(acc.y + b.y, 0.f);
    ((float2*)g_h1)[node * 32 + lane] = o;
}

// ---------------- GEMM2 (tiled, FFMA2) + fused attention dots ----------------
__global__ void gemm2_kernel(const float* __restrict__ Wg,
                             const float* __restrict__ att_src,
                             const float* __restrict__ att_dst, int n) {
    __shared__ float hs[32 * HID];   // 8 KB
    int tid = threadIdx.x, q = tid & 63, rg = tid >> 6, lane = tid & 31;
    int rowbase = blockIdx.x * 32;
    const float4* h1_4 = (const float4*)g_h1;
    float4* hs4 = (float4*)hs;
    for (int l = tid; l < 512; l += 256) {
        int r = l >> 4, c4 = l & 15;
        int row = rowbase + r;
        hs4[l] = (row < n) ? h1_4[row * 16 + c4] : make_float4(0.f, 0.f, 0.f, 0.f);
    }
    __syncthreads();
    u64 accXY[8], accZW[8];
#pragma unroll
    for (int j = 0; j < 8; j++) { accXY[j] = 0ull; accZW[j] = 0ull; }
    const float4* Wg4 = (const float4*)Wg;
#pragma unroll 4
    for (int k = 0; k < HID; k++) {
        float4 w = Wg4[k * 64 + q];
        u64 wxy = pack2(w.x, w.y), wzw = pack2(w.z, w.w);
#pragma unroll
        for (int j = 0; j < 8; j++) {
            float hv = hs[(rg * 8 + j) * HID + k];
            u64 hv2 = pack2(hv, hv);
            ffma2(accXY[j], hv2, wxy);
            ffma2(accZW[j], hv2, wzw);
        }
    }
    float4* z4 = (float4*)g_z;
    float4 asq = ((const float4*)att_src)[q];
    float4 adq = ((const float4*)att_dst)[q];
    float ps[8], pd[8];
#pragma unroll
    for (int j = 0; j < 8; j++) {
        float2 lo = unpack2(accXY[j]), hi = unpack2(accZW[j]);
        float4 a = make_float4(lo.x, lo.y, hi.x, hi.y);
        int row = rowbase + rg * 8 + j;
        if (row < n) z4[row * 64 + q] = a;
        ps[j] = a.x * asq.x + a.y * asq.y + a.z * asq.z + a.w * asq.w;
        pd[j] = a.x * adq.x + a.y * adq.y + a.z * adq.z + a.w * adq.w;
    }
#pragma unroll
    for (int off = 8; off; off >>= 1) {
#pragma unroll
        for (int j = 0; j < 8; j++) {
            ps[j] += __shfl_xor_sync(0xffffffffu, ps[j], off);
            pd[j] += __shfl_xor_sync(0xffffffffu, pd[j], off);
        }
    }
    int head = q >> 4;
    if ((lane & 15) == 0) {
#pragma unroll
        for (int j = 0; j < 8; j++) {
            int row = rowbase + rg * 8 + j;
            if (row < n) { g_as[row * 4 + head] = ps[j]; g_ad[row * 4 + head] = pd[j]; }
        }
    }
}

// ---------------- GAT aggregate: max pass, then fused exp/agg pass ----------------
__global__ void gat_agg_kernel(const float* __restrict__ b_gat, int n) {
    int node = (blockIdx.x * blockDim.x + threadIdx.x) >> 5;
    int lane = threadIdx.x & 31;
    if (node >= n) return;
    int start = g_row_ptr[node], end = g_row_ptr[node + 1];
    const float4* as4 = (const float4*)g_as;
    float4 ad = ((const float4*)g_ad)[node];

    // pass 1: per-head max (lane-parallel)
    float m0 = -1e30f, m1 = -1e30f, m2 = -1e30f, m3 = -1e30f;
    for (int e = start + lane; e < end; e += 32) {
        int s = g_csr[e];
        float4 a = as4[s];
        m0 = fmaxf(m0, lrelu(a.x + ad.x));
        m1 = fmaxf(m1, lrelu(a.y + ad.y));
        m2 = fmaxf(m2, lrelu(a.z + ad.z));
        m3 = fmaxf(m3, lrelu(a.w + ad.w));
    }
#pragma unroll
    for (int off = 16; off; off >>= 1) {
        m0 = fmaxf(m0, __shfl_xor_sync(0xffffffffu, m0, off));
        m1 = fmaxf(m1, __shfl_xor_sync(0xffffffffu, m1, off));
        m2 = fmaxf(m2, __shfl_xor_sync(0xffffffffu, m2, off));
        m3 = fmaxf(m3, __shfl_xor_sync(0xffffffffu, m3, off));
    }

    // pass 2 (fused, software-pipelined): unnormalized ex*z + ex sums
    const float4* z4 = (const float4*)g_z;
    float4 accA = make_float4(0.f, 0.f, 0.f, 0.f);
    float4 accB = make_float4(0.f, 0.f, 0.f, 0.f);
    float d0 = 0.f, d1 = 0.f, d2 = 0.f, d3 = 0.f;
    int s_cur = (start < end) ? g_csr[start] : 0;
    float4 a_cur = (start < end) ? as4[s_cur] : make_float4(0.f, 0.f, 0.f, 0.f);
    for (int e = start; e < end; e++) {
        int s = s_cur;
        float4 a = a_cur;
        if (e + 1 < end) { s_cur = g_csr[e + 1]; a_cur = as4[s_cur]; }
        float e0 = __expf(lrelu(a.x + ad.x) - m0);
        float e1 = __expf(lrelu(a.y + ad.y) - m1);
        float e2 = __expf(lrelu(a.z + ad.z) - m2);
        float e3 = __expf(lrelu(a.w + ad.w) - m3);
        d0 += e0; d1 += e1; d2 += e2; d3 += e3;
        float4 za = z4[s * 64 + lane];        // heads 0/1
        float4 zb = z4[s * 64 + 32 + lane];   // heads 2/3
        float eA = (lane < 16) ? e0 : e1;
        float eB = (lane < 16) ? e2 : e3;
        accA.x += eA * za.x; accA.y += eA * za.y; accA.z += eA * za.z; accA.w += eA * za.w;
        accB.x += eB * zb.x; accB.y += eB * zb.y; accB.z += eB * zb.z; accB.w += eB * zb.w;
    }
    float rA = (lane < 16) ? (1.f / d0) : (1.f / d1);
    float rB = (lane < 16) ? (1.f / d2) : (1.f / d3);
    float4 s4;
    s4.x = accA.x * rA + accB.x * rB;
    s4.y = accA.y * rA + accB.y * rB;
    s4.z = accA.z * rA + accB.z * rB;
    s4.w = accA.w * rA + accB.w * rB;
    s4.x += __shfl_xor_sync(0xffffffffu, s4.x, 16);
    s4.y += __shfl_xor_sync(0xffffffffu, s4.y, 16);
    s4.z += __shfl_xor_sync(0xffffffffu, s4.z, 16);
    s4.w += __shfl_xor_sync(0xffffffffu, s4.w, 16);
    int c = lane & 15;
    float4 b = ((const float4*)b_gat)[c];
    float4 o;
    o.x = fmaxf(0.25f * s4.x + b.x, 0.f);
    o.y = fmaxf(0.25f * s4.y + b.y, 0.f);
    o.z = fmaxf(0.25f * s4.z + b.z, 0.f);
    o.w = fmaxf(0.25f * s4.w + b.w, 0.f);
    if (lane < 16) ((float4*)g_h2)[node * 16 + c] = o;
}

// ---------------- final (tiled, FFMA2): patch GEMM + residual + LayerNorm ----------------
__global__ void final_kernel(const float* __restrict__ Wp, const float* __restrict__ b_patch,
                             const float* __restrict__ gamma, const float* __restrict__ beta,
                             float* __restrict__ out, int n) {
    __shared__ float Ws[HID * HID];    // 16 KB
    __shared__ float hs[128 * HID];    // 32 KB
    int tid = threadIdx.x, q = tid & 15, rg = tid >> 4;
    for (int i = tid; i < HID * HID; i += 256) Ws[i] = Wp[i];
    int rowbase = blockIdx.x * 128;
    const float4* h1_4 = (const float4*)g_h1;
    float4* hs4 = (float4*)hs;
    for (int l = tid; l < 2048; l += 256) {
        int r = l >> 4, c4 = l & 15;
        int row = rowbase + r;
        hs4[l] = (row < n) ? h1_4[row * 16 + c4] : make_float4(0.f, 0.f, 0.f, 0.f);
    }
    __syncthreads();
    u64 accXY[8], accZW[8];
#pragma unroll
    for (int j = 0; j < 8; j++) { accXY[j] = 0ull; accZW[j] = 0ull; }
    const float4* Ws4 = (const float4*)Ws;
#pragma unroll 4
    for (int k = 0; k < HID; k++) {
        float4 w = Ws4[k * 16 + q];
        u64 wxy = pack2(w.x, w.y), wzw = pack2(w.z, w.w);
#pragma unroll
        for (int j = 0; j < 8; j++) {
            float hv = hs[(rg * 8 + j) * HID + k];
            u64 hv2 = pack2(hv, hv);
            ffma2(accXY[j], hv2, wxy);
            ffma2(accZW[j], hv2, wzw);
        }
    }
    const float4* h2_4 = (const float4*)g_h2;
    float4 bp  = ((const float4*)b_patch)[q];
    float4 g4  = ((const float4*)gamma)[q];
    float4 bt4 = ((const float4*)beta)[q];
    float4* out4 = (float4*)out;
#pragma unroll
    for (int j = 0; j < 8; j++) {
        int row = rowbase + rg * 8 + j;
        float2 lo = unpack2(accXY[j]), hi = unpack2(accZW[j]);
        float4 h1v = hs4[(rg * 8 + j) * 16 + q];
        float4 h2v = (row < n) ? h2_4[row * 16 + q] : make_float4(0.f, 0.f, 0.f, 0.f);
        float4 h;
        h.x = h1v.x + h2v.x + lo.x + bp.x;
        h.y = h1v.y + h2v.y + lo.y + bp.y;
        h.z = h1v.z + h2v.z + hi.x + bp.z;
        h.w = h1v.w + h2v.w + hi.y + bp.w;
        float s  = h.x + h.y + h.z + h.w;
        float sq = h.x * h.x + h.y * h.y + h.z * h.z + h.w * h.w;
#pragma unroll
        for (int off = 8; off; off >>= 1) {
            s  += __shfl_xor_sync(0xffffffffu, s, off);
            sq += __shfl_xor_sync(0xffffffffu, sq, off);
        }
        float mu = s * (1.f / 64.f);
        float var = sq * (1.f / 64.f) - mu * mu;
        float rstd = rsqrtf(var + 1e-5f);
        if (row < n) {
            float4 o;
            o.x = (h.x - mu) * rstd * g4.x + bt4.x;
            o.y = (h.y - mu) * rstd * g4.y + bt4.y;
            o.z = (h.z - mu) * rstd * g4.z + bt4.z;
            o.w = (h.w - mu) * rstd * g4.w + bt4.w;
            out4[row * 16 + q] = o;
        }
    }
}

// ---------------- launch ----------------
extern "C" void kernel_launch(void* const* d_in, const int* in_sizes, int n_in,
                              void* d_out, int out_size) {
    const float* x        = (const float*)d_in[0];
    const void*  ei       = d_in[1];
    const float* W_gcn    = (const float*)d_in[2];
    const float* b_gcn    = (const float*)d_in[3];
    const float* W_gat    = (const float*)d_in[4];
    const float* att_src  = (const float*)d_in[5];
    const float* att_dst  = (const float*)d_in[6];
    const float* b_gat    = (const float*)d_in[7];
    const float* W_patch  = (const float*)d_in[8];
    const float* b_patch  = (const float*)d_in[9];
    const float* gamma    = (const float*)d_in[10];
    const float* beta     = (const float*)d_in[11];
    float* out = (float*)d_out;

    int n = in_sizes[0] / INDIM;          // 50000
    int E = in_sizes[1] / 2;              // 400000

    const int T = 256;
    int gN   = (n + T - 1) / T;
    int gE   = (E + T - 1) / T;
    int gEN  = (E + n + T - 1) / T;
    int nb   = (n + 255) / 256;
    int g128 = (n + 127) / 128;
    int g32  = (n + 31) / 32;
    int gWpN = (n * 32 + T - 1) / T;

    detect_kernel<<<1, 256>>>((const int*)ei);
    init_deg_kernel<<<gN, T>>>(n);
    hist_kernel<<<gE, T>>>(ei, E);
    scanA_kernel<<<nb, 256>>>(n);
    scanB_kernel<<<1, 1024>>>(nb, n, E + n);
    scanC_kernel<<<gN, T>>>(n);
    fill_csr_kernel<<<gEN, T>>>(ei, E, n);
    gemm1_kernel<<<g128, T>>>(x, W_gcn, n);
    gcn_agg_kernel<<<gWpN, T>>>(b_gcn, n);
    gemm2_kernel<<<g32, T>>>(W_gat, att_src, att_dst, n);
    gat_agg_kernel<<<gWpN, T>>>(b_gat, n);
    final_kernel<<<g128, T>>>(W_patch, b_patch, gamma, beta, out, n);
}

// round 5
// speedup vs baseline: 1.8866x; 1.0217x over previous
#include <cuda_runtime.h>
#include <cuda_bf16.h>
#include <cuda_fp16.h>
#include <math.h>

#define NN 50000
#define EE 400000
#define HID 64
#define HEADS 4
#define INDIM 128

typedef unsigned long long u64;

struct __align__(8) half4 { __half2 a, b; };

// ---------------- scratch (no allocations allowed) ----------------
__device__ int   g_is64;
__device__ int   g_deg[NN];
__device__ int   g_row_ptr[NN + 1];
__device__ int   g_cursor[NN];
__device__ int   g_csr[EE + NN];
__device__ int   g_pdst[EE + NN];
__device__ int   g_bsum[1024];
__device__ float g_dinv[NN];
__device__ __align__(16) float   g_ws[HEADS * HID];   // W_h @ att_src[h]
__device__ __align__(16) float   g_wd[HEADS * HID];   // W_h @ att_dst[h]
__device__ __align__(16) float   g_xw[NN * HID];
__device__ __align__(16) float   g_h1[NN * HID];
__device__ __align__(16) __half2 g_h1h[NN * 32];      // fp16 copy of h1, half2/lane
__device__ __align__(16) float   g_as[NN * HEADS];
__device__ __align__(16) float   g_ad[NN * HEADS];
__device__ __align__(16) float   g_m[NN * HEADS];
__device__ __align__(16) half4   g_ex[EE + NN];       // per-edge exp weights (4 heads)
__device__ __align__(16) float   g_u[NN * HEADS * HID]; // alpha-aggregated h1 per head
__device__ __align__(16) float   g_h2[NN * HID];

// ---------------- packed f32x2 helpers (SASS FFMA2 path) ----------------
__device__ __forceinline__ u64 pack2(float lo, float hi) {
    u64 r; asm("mov.b64 %0, {%1, %2};" : "=l"(r) : "f"(lo), "f"(hi)); return r;
}
__device__ __forceinline__ void ffma2(u64& d, u64 a, u64 b) {
    asm("fma.rn.f32x2 %0, %1, %2, %0;" : "+l"(d) : "l"(a), "l"(b));
}
__device__ __forceinline__ float2 unpack2(u64 v) {
    float2 f; asm("mov.b64 {%0, %1}, %2;" : "=f"(f.x), "=f"(f.y) : "l"(v)); return f;
}

// ---------------- helpers ----------------
__device__ __forceinline__ int load_edge(const void* ei, long long idx) {
    if (g_is64) return (int)((const long long*)ei)[idx];
    return ((const int*)ei)[idx];
}
__device__ __forceinline__ float lrelu(float v) { return fmaxf(v, 0.2f * v); }

// ---------------- prep: detect dtype + init deg + rank-1 attention weights ----------------
__global__ void prep_kernel(const int* ei_words, const float* __restrict__ Wg,
                            const float* __restrict__ att_src,
                            const float* __restrict__ att_dst, int n) {
    int i = blockIdx.x * blockDim.x + threadIdx.x;
    if (i < n) g_deg[i] = 1;
    if (blockIdx.x == 0) {
        __shared__ int cnt;
        if (threadIdx.x == 0) cnt = 0;
        __syncthreads();
        int c = 0;
        for (int k = threadIdx.x; k < 2048; k += blockDim.x)
            if (ei_words[2 * k + 1] != 0) c++;
        atomicAdd(&cnt, c);
        __syncthreads();
        if (threadIdx.x == 0) g_is64 = (cnt < 100) ? 1 : 0;
    }
    if (blockIdx.x == 1) {
        int t = threadIdx.x;          // t = h*64 + k
        int h = t >> 6, k = t & 63;
        float ss = 0.f, sd = 0.f;
        for (int c = 0; c < HID; c++) {
            float w = Wg[k * 256 + h * 64 + c];
            ss += w * att_src[h * 64 + c];
            sd += w * att_dst[h * 64 + c];
        }
        g_ws[t] = ss;
        g_wd[t] = sd;
    }
}

// ---------------- degree histogram ----------------
__global__ void hist_kernel(const void* ei, int E) {
    int i = blockIdx.x * blockDim.x + threadIdx.x;
    if (i >= E) return;
    int d = load_edge(ei, (long long)E + i);
    atomicAdd(&g_deg[d], 1);
}

// ---------------- decoupled 3-phase scan ----------------
__global__ void scanA_kernel(int n) {
    __shared__ int wsum[8];
    int t = threadIdx.x, lane = t & 31, wid = t >> 5;
    int i = blockIdx.x * 256 + t;
    int v = (i < n) ? g_deg[i] : 0;
    int x = v;
#pragma unroll
    for (int off = 1; off < 32; off <<= 1) {
        int y = __shfl_up_sync(0xffffffffu, x, off);
        if (lane >= off) x += y;
    }
    if (lane == 31) wsum[wid] = x;
    __syncthreads();
    if (wid == 0) {
        int y = (lane < 8) ? wsum[lane] : 0;
#pragma unroll
        for (int off = 1; off < 8; off <<= 1) {
            int z = __shfl_up_sync(0xffffffffu, y, off);
            if (lane >= off) y += z;
        }
        if (lane < 8) wsum[lane] = y;
    }
    __syncthreads();
    int excl_w = wid ? wsum[wid - 1] : 0;
    int incl = x + excl_w;
    if (i < n) {
        g_row_ptr[i] = incl - v;
        g_dinv[i] = rsqrtf((float)v);
    }
    if (t == 255) g_bsum[blockIdx.x] = incl;
}

__global__ void scanB_kernel(int nb, int n, int total) {
    __shared__ int wsum[32];
    int t = threadIdx.x, lane = t & 31, wid = t >> 5;
    int v = (t < nb) ? g_bsum[t] : 0;
    int x = v;
#pragma unroll
    for (int off = 1; off < 32; off <<= 1) {
        int y = __shfl_up_sync(0xffffffffu, x, off);
        if (lane >= off) x += y;
    }
    if (lane == 31) wsum[wid] = x;
    __syncthreads();
    if (wid == 0) {
        int y = wsum[lane];
#pragma unroll
        for (int off = 1; off < 32; off <<= 1) {
            int z = __shfl_up_sync(0xffffffffu, y, off);
            if (lane >= off) y += z;
        }
        wsum[lane] = y;
    }
    __syncthreads();
    int excl_w = wid ? wsum[wid - 1] : 0;
    if (t < nb) g_bsum[t] = x + excl_w - v;
    if (t == 0) g_row_ptr[n] = total;
}

__global__ void scanC_kernel(int n) {
    int i = blockIdx.x * blockDim.x + threadIdx.x;
    if (i >= n) return;
    int rp = g_row_ptr[i] + g_bsum[i >> 8];
    g_row_ptr[i] = rp;
    g_cursor[i] = rp;
}

// ---------------- CSR fill (edges + self-loops); also per-position dst ----------------
__global__ void fill_csr_kernel(const void* ei, int E, int n) {
    int i = blockIdx.x * blockDim.x + threadIdx.x;
    int total = E + n;
    if (i >= total) return;
    int s, d;
    if (i < E) { s = load_edge(ei, i); d = load_edge(ei, (long long)E + i); }
    else { s = d = i - E; }
    int pos = atomicAdd(&g_cursor[d], 1);
    g_csr[pos] = s;
    g_pdst[pos] = d;
}

// ---------------- GEMM1 (tiled, FFMA2): xw = x @ W_gcn  [N,128]@[128,64] ----------------
__global__ void gemm1_kernel(const float* __restrict__ x, const float* __restrict__ W, int n) {
    __shared__ float Ws[INDIM * HID];   // 32 KB
    __shared__ float xs[128 * 32];      // 16 KB
    int tid = threadIdx.x, q = tid & 15, rg = tid >> 4;
    for (int i = tid; i < INDIM * HID; i += 256) Ws[i] = W[i];
    int rowbase = blockIdx.x * 128;
    u64 accXY[8], accZW[8];
#pragma unroll
    for (int j = 0; j < 8; j++) { accXY[j] = 0ull; accZW[j] = 0ull; }
    const float4* x4 = (const float4*)x;
    float4* xs4 = (float4*)xs;
    const float4* Ws4 = (const float4*)Ws;
    for (int ch = 0; ch < 4; ch++) {
        __syncthreads();
        for (int l = tid; l < 1024; l += 256) {
            int r = l >> 3, c4 = l & 7;
            int row = rowbase + r;
            float4 v = make_float4(0.f, 0.f, 0.f, 0.f);
            if (row < n) v = x4[row * 32 + ch * 8 + c4];
            xs4[r * 8 + c4] = v;
        }
        __syncthreads();
#pragma unroll 4
        for (int kk = 0; kk < 32; kk++) {
            float4 w = Ws4[(ch * 32 + kk) * 16 + q];
            u64 wxy = pack2(w.x, w.y), wzw = pack2(w.z, w.w);
#pragma unroll
            for (int j = 0; j < 8; j++) {
                float xv = xs[(rg * 8 + j) * 32 + kk];
                u64 xv2 = pack2(xv, xv);
                ffma2(accXY[j], xv2, wxy);
                ffma2(accZW[j], xv2, wzw);
            }
        }
    }
    float4* xw4 = (float4*)g_xw;
#pragma unroll
    for (int j = 0; j < 8; j++) {
        int row = rowbase + rg * 8 + j;
        if (row < n) {
            float2 lo = unpack2(accXY[j]), hi = unpack2(accZW[j]);
            xw4[row * 16 + q] = make_float4(lo.x, lo.y, hi.x, hi.y);
        }
    }
}

// ---------------- GCN aggregate + fused rank-1 attention dots ----------------
__global__ void gcn_agg_kernel(const float* __restrict__ b_gcn, int n) {
    int node = (blockIdx.x * blockDim.x + threadIdx.x) >> 5;
    int lane = threadIdx.x & 31;
    if (node >= n) return;
    int start = g_row_ptr[node], end = g_row_ptr[node + 1];
    float dn = g_dinv[node];
    const float2* xw2 = (const float2*)g_xw;
    float2 acc = make_float2(0.f, 0.f);
    int s_next = (start < end) ? g_csr[start] : 0;
    for (int e = start; e < end; e++) {
        int s = s_next;
        if (e + 1 < end) s_next = g_csr[e + 1];
        float w = g_dinv[s] * dn;
        float2 v = xw2[s * 32 + lane];
        acc.x += w * v.x; acc.y += w * v.y;
    }
    float2 b = ((const float2*)b_gcn)[lane];
    float2 o;
    o.x = fmaxf(acc.x + b.x, 0.f);   // channel 2*lane
    o.y = fmaxf(acc.y + b.y, 0.f);   // channel 2*lane+1
    ((float2*)g_h1)[node * 32 + lane] = o;
    g_h1h[node * 32 + lane] = __floats2half2_rn(o.x, o.y);

    // fused attention dots: a_s[h] = h1 . w_s[h], a_d[h] = h1 . w_d[h]
    const float2* ws2 = (const float2*)g_ws;
    const float2* wd2 = (const float2*)g_wd;
    float p[8];
#pragma unroll
    for (int h = 0; h < 4; h++) {
        float2 ws = ws2[h * 32 + lane];
        float2 wd = wd2[h * 32 + lane];
        p[h]     = o.x * ws.x + o.y * ws.y;
        p[4 + h] = o.x * wd.x + o.y * wd.y;
    }
#pragma unroll
    for (int off = 16; off; off >>= 1) {
#pragma unroll
        for (int j = 0; j < 8; j++) p[j] += __shfl_xor_sync(0xffffffffu, p[j], off);
    }
    if (lane == 0) {
        ((float4*)g_as)[node] = make_float4(p[0], p[1], p[2], p[3]);
        ((float4*)g_ad)[node] = make_float4(p[4], p[5], p[6], p[7]);
    }
}

// ---------------- GAT pass 1: per-node per-head max ----------------
__global__ void gat_max_kernel(int n) {
    int node = (blockIdx.x * blockDim.x + threadIdx.x) >> 5;
    int lane = threadIdx.x & 31;
    if (node >= n) return;
    int start = g_row_ptr[node], end = g_row_ptr[node + 1];
    const float4* as4 = (const float4*)g_as;
    float4 ad = ((const float4*)g_ad)[node];
    float m0 = -1e30f, m1 = -1e30f, m2 = -1e30f, m3 = -1e30f;
    for (int e = start + lane; e < end; e += 32) {
        int s = g_csr[e];
        float4 a = as4[s];
        m0 = fmaxf(m0, lrelu(a.x + ad.x));
        m1 = fmaxf(m1, lrelu(a.y + ad.y));
        m2 = fmaxf(m2, lrelu(a.z + ad.z));
        m3 = fmaxf(m3, lrelu(a.w + ad.w));
    }
#pragma unroll
    for (int off = 16; off; off >>= 1) {
        m0 = fmaxf(m0, __shfl_xor_sync(0xffffffffu, m0, off));
        m1 = fmaxf(m1, __shfl_xor_sync(0xffffffffu, m1, off));
        m2 = fmaxf(m2, __shfl_xor_sync(0xffffffffu, m2, off));
        m3 = fmaxf(m3, __shfl_xor_sync(0xffffffffu, m3, off));
    }
    if (lane == 0) ((float4*)g_m)[node] = make_float4(m0, m1, m2, m3);
}

// ---------------- GAT pass 2: edge-parallel exp weights (<=1, stored fp16) ----------------
__global__ void gat_exp_kernel(int total) {
    int p = blockIdx.x * blockDim.x + threadIdx.x;
    if (p >= total) return;
    int s = g_csr[p];
    int d = g_pdst[p];
    float4 a  = ((const float4*)g_as)[s];
    float4 ad = ((const float4*)g_ad)[d];
    float4 m  = ((const float4*)g_m)[d];
    float e0 = __expf(lrelu(a.x + ad.x) - m.x);
    float e1 = __expf(lrelu(a.y + ad.y) - m.y);
    float e2 = __expf(lrelu(a.z + ad.z) - m.z);
    float e3 = __expf(lrelu(a.w + ad.w) - m.w);
    half4 out;
    out.a = __floats2half2_rn(e0, e1);
    out.b = __floats2half2_rn(e2, e3);
    g_ex[p] = out;
}

// ---------------- GAT pass 3: aggregate h1 (fp16) per head, normalize ----------------
__global__ void gat_agg_kernel(int n) {
    int node = (blockIdx.x * blockDim.x + threadIdx.x) >> 5;
    int lane = threadIdx.x & 31;
    if (node >= n) return;
    int start = g_row_ptr[node], end = g_row_ptr[node + 1];
    float acc[8];
#pragma unroll
    for (int i = 0; i < 8; i++) acc[i] = 0.f;
    float d0 = 0.f, d1 = 0.f, d2 = 0.f, d3 = 0.f;
    int s_cur = (start < end) ? g_csr[start] : 0;
    half4 ex_cur = (start < end) ? g_ex[start] : half4{__floats2half2_rn(0.f, 0.f), __floats2half2_rn(0.f, 0.f)};
    for (int e = start; e < end; e++) {
        int s = s_cur;
        half4 exv = ex_cur;
        if (e + 1 < end) { s_cur = g_csr[e + 1]; ex_cur = g_ex[e + 1]; }
        float2 e01 = __half22float2(exv.a);
        float2 e23 = __half22float2(exv.b);
        d0 += e01.x; d1 += e01.y; d2 += e23.x; d3 += e23.y;
        float2 hv = __half22float2(g_h1h[s * 32 + lane]);
        acc[0] += e01.x * hv.x; acc[1] += e01.x * hv.y;
        acc[2] += e01.y * hv.x; acc[3] += e01.y * hv.y;
        acc[4] += e23.x * hv.x; acc[5] += e23.x * hv.y;
        acc[6] += e23.y * hv.x; acc[7] += e23.y * hv.y;
    }
    float r0 = 1.f / d0, r1 = 1.f / d1, r2 = 1.f / d2, r3 = 1.f / d3;
    float2* u2 = (float2*)g_u;
    // u layout: [node][h*64 + k]; lane holds channels 2*lane, 2*lane+1
    u2[node * 128 +       lane] = make_float2(acc[0] * r0, acc[1] * r0);
    u2[node * 128 +  32 + lane] = make_float2(acc[2] * r1, acc[3] * r1);
    u2[node * 128 +  64 + lane] = make_float2(acc[4] * r2, acc[5] * r2);
    u2[node * 128 +  96 + lane] = make_float2(acc[6] * r3, acc[7] * r3);
}

// ---------------- GEMM2b (tiled, FFMA2): h2 = relu(0.25 * u @ Wstack + b_gat) ----------------
// Wstack[h*64+k][c] = W_gat[k][h*64+c]. Chunked over heads (K=4x64).
__global__ void gemm2b_kernel(const float* __restrict__ Wg, const float* __restrict__ b_gat, int n) {
    __shared__ float Wc[HID * HID];    // 16 KB (one head's 64x64 block)
    __shared__ float us[128 * HID];    // 32 KB
    int tid = threadIdx.x, q = tid & 15, rg = tid >> 4;
    int rowbase = blockIdx.x * 128;
    u64 accXY[8], accZW[8];
#pragma unroll
    for (int j = 0; j < 8; j++) { accXY[j] = 0ull; accZW[j] = 0ull; }
    const float4* Wg4 = (const float4*)Wg;
    const float4* u4 = (const float4*)g_u;
    float4* Wc4s = (float4*)Wc;
    float4* us4 = (float4*)us;
    const float4* Wc4 = (const float4*)Wc;
    for (int h = 0; h < 4; h++) {
        __syncthreads();
        for (int i = tid; i < 1024; i += 256) {       // Wc[k][c] = Wg[k][h*64+c]
            int k = i >> 4, j = i & 15;
            Wc4s[i] = Wg4[k * 64 + h * 16 + j];
        }
        for (int i = tid; i < 2048; i += 256) {       // us[r][k] = u[row][h*64+k]
            int r = i >> 4, j = i & 15;
            int row = rowbase + r;
            us4[i] = (row < n) ? u4[row * 64 + h * 16 + j] : make_float4(0.f, 0.f, 0.f, 0.f);
        }
        __syncthreads();
#pragma unroll 4
        for (int k = 0; k < HID; k++) {
            float4 w = Wc4[k * 16 + q];
            u64 wxy = pack2(w.x, w.y), wzw = pack2(w.z, w.w);
#pragma unroll
            for (int j = 0; j < 8; j++) {
                float hv = us[(rg * 8 + j) * HID + k];
                u64 hv2 = pack2(hv, hv);
                ffma2(accXY[j], hv2, wxy);
                ffma2(accZW[j], hv2, wzw);
            }
        }
    }
    float4 b = ((const float4*)b_gat)[q];
    float4* h2_4 = (float4*)g_h2;
#pragma unroll
    for (int j = 0; j < 8; j++) {
        int row = rowbase + rg * 8 + j;
        if (row < n) {
            float2 lo = unpack2(accXY[j]), hi = unpack2(accZW[j]);
            float4 o;
            o.x = fmaxf(0.25f * lo.x + b.x, 0.f);
            o.y = fmaxf(0.25f * lo.y + b.y, 0.f);
            o.z = fmaxf(0.25f * hi.x + b.z, 0.f);
            o.w = fmaxf(0.25f * hi.y + b.w, 0.f);
            h2_4[row * 16 + q] = o;
        }
    }
}

// ---------------- final (tiled, FFMA2): patch GEMM + residual + LayerNorm ----------------
__global__ void final_kernel(const float* __restrict__ Wp, const float* __restrict__ b_patch,
                             const float* __restrict__ gamma, const float* __restrict__ beta,
                             float* __restrict__ out, int n) {
    __shared__ float Ws[HID * HID];    // 16 KB
    __shared__ float hs[128 * HID];    // 32 KB
    int tid = threadIdx.x, q = tid & 15, rg = tid >> 4;
    for (int i = tid; i < HID * HID; i += 256) Ws[i] = Wp[i];
    int rowbase = blockIdx.x * 128;
    const float4* h1_4 = (const float4*)g_h1;
    float4* hs4 = (float4*)hs;
    for (int l = tid; l < 2048; l += 256) {
        int r = l >> 4, c4 = l & 15;
        int row = rowbase + r;
        hs4[l] = (row < n) ? h1_4[row * 16 + c4] : make_float4(0.f, 0.f, 0.f, 0.f);
    }
    __syncthreads();
    u64 accXY[8], accZW[8];
#pragma unroll
    for (int j = 0; j < 8; j++) { accXY[j] = 0ull; accZW[j] = 0ull; }
    const float4* Ws4 = (const float4*)Ws;
#pragma unroll 4
    for (int k = 0; k < HID; k++) {
        float4 w = Ws4[k * 16 + q];
        u64 wxy = pack2(w.x, w.y), wzw = pack2(w.z, w.w);
#pragma unroll
        for (int j = 0; j < 8; j++) {
            float hv = hs[(rg * 8 + j) * HID + k];
            u64 hv2 = pack2(hv, hv);
            ffma2(accXY[j], hv2, wxy);
            ffma2(accZW[j], hv2, wzw);
        }
    }
    const float4* h2_4 = (const float4*)g_h2;
    float4 bp  = ((const float4*)b_patch)[q];
    float4 g4  = ((const float4*)gamma)[q];
    float4 bt4 = ((const float4*)beta)[q];
    float4* out4 = (float4*)out;
#pragma unroll
    for (int j = 0; j < 8; j++) {
        int row = rowbase + rg * 8 + j;
        float2 lo = unpack2(accXY[j]), hi = unpack2(accZW[j]);
        float4 h1v = hs4[(rg * 8 + j) * 16 + q];
        float4 h2v = (row < n) ? h2_4[row * 16 + q] : make_float4(0.f, 0.f, 0.f, 0.f);
        float4 h;
        h.x = h1v.x + h2v.x + lo.x + bp.x;
        h.y = h1v.y + h2v.y + lo.y + bp.y;
        h.z = h1v.z + h2v.z + hi.x + bp.z;
        h.w = h1v.w + h2v.w + hi.y + bp.w;
        float s  = h.x + h.y + h.z + h.w;
        float sq = h.x * h.x + h.y * h.y + h.z * h.z + h.w * h.w;
#pragma unroll
        for (int off = 8; off; off >>= 1) {
            s  += __shfl_xor_sync(0xffffffffu, s, off);
            sq += __shfl_xor_sync(0xffffffffu, sq, off);
        }
        float mu = s * (1.f / 64.f);
        float var = sq * (1.f / 64.f) - mu * mu;
        float rstd = rsqrtf(var + 1e-5f);
        if (row < n) {
            float4 o;
            o.x = (h.x - mu) * rstd * g4.x + bt4.x;
            o.y = (h.y - mu) * rstd * g4.y + bt4.y;
            o.z = (h.z - mu) * rstd * g4.z + bt4.z;
            o.w = (h.w - mu) * rstd * g4.w + bt4.w;
            out4[row * 16 + q] = o;
        }
    }
}

// ---------------- launch ----------------
extern "C" void kernel_launch(void* const* d_in, const int* in_sizes, int n_in,
                              void* d_out, int out_size) {
    const float* x        = (const float*)d_in[0];
    const void*  ei       = d_in[1];
    const float* W_gcn    = (const float*)d_in[2];
    const float* b_gcn    = (const float*)d_in[3];
    const float* W_gat    = (const float*)d_in[4];
    const float* att_src  = (const float*)d_in[5];
    const float* att_dst  = (const float*)d_in[6];
    const float* b_gat    = (const float*)d_in[7];
    const float* W_patch  = (const float*)d_in[8];
    const float* b_patch  = (const float*)d_in[9];
    const float* gamma    = (const float*)d_in[10];
    const float* beta     = (const float*)d_in[11];
    float* out = (float*)d_out;

    int n = in_sizes[0] / INDIM;          // 50000
    int E = in_sizes[1] / 2;              // 400000

    const int T = 256;
    int gN   = (n + T - 1) / T;
    int gE   = (E + T - 1) / T;
    int gEN  = (E + n + T - 1) / T;
    int nb   = (n + 255) / 256;
    int g128 = (n + 127) / 128;
    int gWpN = (n * 32 + T - 1) / T;

    prep_kernel<<<gN, T>>>((const int*)ei, W_gat, att_src, att_dst, n);
    hist_kernel<<<gE, T>>>(ei, E);
    scanA_kernel<<<nb, 256>>>(n);
    scanB_kernel<<<1, 1024>>>(nb, n, E + n);
    scanC_kernel<<<gN, T>>>(n);
    fill_csr_kernel<<<gEN, T>>>(ei, E, n);
    gemm1_kernel<<<g128, T>>>(x, W_gcn, n);
    gcn_agg_kernel<<<gWpN, T>>>(b_gcn, n);
    gat_max_kernel<<<gWpN, T>>>(n);
    gat_exp_kernel<<<gEN, T>>>(E + n);
    gat_agg_kernel<<<gWpN, T>>>(n);
    gemm2b_kernel<<<g128, T>>>(W_gat, b_gat, n);
    final_kernel<<<g128, T>>>(W_patch, b_patch, gamma, beta, out, n);
}

// round 6
// speedup vs baseline: 2.1054x; 1.1160x over previous
#include <cuda_runtime.h>
#include <cuda_bf16.h>
#include <cuda_fp16.h>
#include <math.h>

#define NN 50000
#define EE 400000
#define HID 64
#define HEADS 4
#define INDIM 128

typedef unsigned long long u64;

struct __align__(8) half4 { __half2 a, b; };

// ---------------- scratch (no allocations allowed) ----------------
__device__ int   g_is64;
__device__ int   g_deg[NN];           // zero at load; scanA resets to zero each run
__device__ int   g_row_ptr[NN + 1];
__device__ int   g_cursor[NN];
__device__ int   g_csr[EE + NN];
__device__ int   g_pdst[EE + NN];
__device__ int   g_bsum[1024];
__device__ float g_dinv[NN];
__device__ __align__(16) float   g_ws[HEADS * HID];
__device__ __align__(16) float   g_wd[HEADS * HID];
__device__ __align__(16) float   g_xw[NN * HID];
__device__ __align__(16) float   g_h1[NN * HID];
__device__ __align__(16) __half2 g_h1h[NN * 32];
__device__ __align__(16) float   g_as[NN * HEADS];
__device__ __align__(16) float   g_ad[NN * HEADS];
__device__ __align__(16) float   g_m[NN * HEADS];
__device__ __align__(16) half4   g_ex[EE + NN];
__device__ __align__(16) float   g_u[NN * HEADS * HID];
__device__ __align__(16) float   g_h2[NN * HID];
__device__ __align__(16) float   g_hp[NN * HID];

// ---------------- packed f32x2 helpers (SASS FFMA2 path) ----------------
__device__ __forceinline__ u64 pack2(float lo, float hi) {
    u64 r; asm("mov.b64 %0, {%1, %2};" : "=l"(r) : "f"(lo), "f"(hi)); return r;
}
__device__ __forceinline__ void ffma2(u64& d, u64 a, u64 b) {
    asm("fma.rn.f32x2 %0, %1, %2, %0;" : "+l"(d) : "l"(a), "l"(b));
}
__device__ __forceinline__ float2 unpack2(u64 v) {
    float2 f; asm("mov.b64 {%0, %1}, %2;" : "=f"(f.x), "=f"(f.y) : "l"(v)); return f;
}

__device__ __forceinline__ int load_edge(const void* ei, long long idx) {
    if (g_is64) return (int)((const long long*)ei)[idx];
    return ((const int*)ei)[idx];
}
__device__ __forceinline__ float lrelu(float v) { return fmaxf(v, 0.2f * v); }

// ---------------- prep: dtype detect + rank-1 attention weights (1 block) ----------------
__global__ void prep_kernel(const int* ei_words, const float* __restrict__ Wg,
                            const float* __restrict__ att_src,
                            const float* __restrict__ att_dst) {
    __shared__ int cnt;
    int t = threadIdx.x;
    if (t == 0) cnt = 0;
    __syncthreads();
    int c = 0;
    for (int k = t; k < 2048; k += 256)
        if (ei_words[2 * k + 1] != 0) c++;
    atomicAdd(&cnt, c);
    // rank-1 weights: t = h*64 + k
    int h = t >> 6, k = t & 63;
    float ss = 0.f, sd = 0.f;
    for (int ch = 0; ch < HID; ch++) {
        float w = Wg[k * 256 + h * 64 + ch];
        ss += w * att_src[h * 64 + ch];
        sd += w * att_dst[h * 64 + ch];
    }
    g_ws[t] = ss;
    g_wd[t] = sd;
    __syncthreads();
    if (t == 0) g_is64 = (cnt < 100) ? 1 : 0;
}

// ---------------- degree histogram (deg starts at 0; self-loop added in scanA) ----------------
__global__ void hist_kernel(const void* ei, int E) {
    int i = blockIdx.x * blockDim.x + threadIdx.x;
    if (i >= E) return;
    int d = load_edge(ei, (long long)E + i);
    atomicAdd(&g_deg[d], 1);
}

// ---------------- scanA: per-256-block exclusive scan of (deg+1); resets deg ----------------
__global__ void scanA_kernel(int n) {
    __shared__ int wsum[8];
    int t = threadIdx.x, lane = t & 31, wid = t >> 5;
    int i = blockIdx.x * 256 + t;
    int v = (i < n) ? (g_deg[i] + 1) : 0;
    int x = v;
#pragma unroll
    for (int off = 1; off < 32; off <<= 1) {
        int y = __shfl_up_sync(0xffffffffu, x, off);
        if (lane >= off) x += y;
    }
    if (lane == 31) wsum[wid] = x;
    __syncthreads();
    if (wid == 0) {
        int y = (lane < 8) ? wsum[lane] : 0;
#pragma unroll
        for (int off = 1; off < 8; off <<= 1) {
            int z = __shfl_up_sync(0xffffffffu, y, off);
            if (lane >= off) y += z;
        }
        if (lane < 8) wsum[lane] = y;
    }
    __syncthreads();
    int excl_w = wid ? wsum[wid - 1] : 0;
    int incl = x + excl_w;
    if (i < n) {
        g_row_ptr[i] = incl - v;
        g_dinv[i] = rsqrtf((float)v);
        g_deg[i] = 0;                      // reset for next graph replay
    }
    if (t == 255) g_bsum[blockIdx.x] = incl;
}

// ---------------- scanC: block b adds sum(bsum[0..b)); writes row_ptr + cursor ----------------
__global__ void scanC_kernel(int n, int total) {
    __shared__ int ssum[8];
    __shared__ int s_off;
    int t = threadIdx.x, b = blockIdx.x;
    int v = (t < b) ? g_bsum[t] : 0;       // nb <= 256
#pragma unroll
    for (int off = 16; off; off >>= 1) v += __shfl_xor_sync(0xffffffffu, v, off);
    if ((t & 31) == 0) ssum[t >> 5] = v;
    __syncthreads();
    if (t == 0) {
        int a = 0;
#pragma unroll
        for (int w = 0; w < 8; w++) a += ssum[w];
        s_off = a;
    }
    __syncthreads();
    int i = b * 256 + t;
    if (i < n) {
        int rp = g_row_ptr[i] + s_off;
        g_row_ptr[i] = rp;
        g_cursor[i] = rp;
    }
    if (b == 0 && t == 0) g_row_ptr[n] = total;
}

// ---------------- CSR fill (edges + self-loops) ----------------
__global__ void fill_csr_kernel(const void* ei, int E, int n) {
    int i = blockIdx.x * blockDim.x + threadIdx.x;
    int total = E + n;
    if (i >= total) return;
    int s, d;
    if (i < E) { s = load_edge(ei, i); d = load_edge(ei, (long long)E + i); }
    else { s = d = i - E; }
    int pos = atomicAdd(&g_cursor[d], 1);
    g_csr[pos] = s;
    g_pdst[pos] = d;
}

// ---------------- GEMM1 (tiled, FFMA2): xw = x @ W_gcn ----------------
__global__ void gemm1_kernel(const float* __restrict__ x, const float* __restrict__ W, int n) {
    __shared__ float Ws[INDIM * HID];
    __shared__ float xs[128 * 32];
    int tid = threadIdx.x, q = tid & 15, rg = tid >> 4;
    for (int i = tid; i < INDIM * HID; i += 256) Ws[i] = W[i];
    int rowbase = blockIdx.x * 128;
    u64 accXY[8], accZW[8];
#pragma unroll
    for (int j = 0; j < 8; j++) { accXY[j] = 0ull; accZW[j] = 0ull; }
    const float4* x4 = (const float4*)x;
    float4* xs4 = (float4*)xs;
    const float4* Ws4 = (const float4*)Ws;
    for (int ch = 0; ch < 4; ch++) {
        __syncthreads();
        for (int l = tid; l < 1024; l += 256) {
            int r = l >> 3, c4 = l & 7;
            int row = rowbase + r;
            float4 v = make_float4(0.f, 0.f, 0.f, 0.f);
            if (row < n) v = x4[row * 32 + ch * 8 + c4];
            xs4[r * 8 + c4] = v;
        }
        __syncthreads();
#pragma unroll 4
        for (int kk = 0; kk < 32; kk++) {
            float4 w = Ws4[(ch * 32 + kk) * 16 + q];
            u64 wxy = pack2(w.x, w.y), wzw = pack2(w.z, w.w);
#pragma unroll
            for (int j = 0; j < 8; j++) {
                float xv = xs[(rg * 8 + j) * 32 + kk];
                u64 xv2 = pack2(xv, xv);
                ffma2(accXY[j], xv2, wxy);
                ffma2(accZW[j], xv2, wzw);
            }
        }
    }
    float4* xw4 = (float4*)g_xw;
#pragma unroll
    for (int j = 0; j < 8; j++) {
        int row = rowbase + rg * 8 + j;
        if (row < n) {
            float2 lo = unpack2(accXY[j]), hi = unpack2(accZW[j]);
            xw4[row * 16 + q] = make_float4(lo.x, lo.y, hi.x, hi.y);
        }
    }
}

// ---------------- GCN aggregate + fused rank-1 attention dots ----------------
__global__ void gcn_agg_kernel(const float* __restrict__ b_gcn, int n) {
    int node = (blockIdx.x * blockDim.x + threadIdx.x) >> 5;
    int lane = threadIdx.x & 31;
    if (node >= n) return;
    int start = g_row_ptr[node], end = g_row_ptr[node + 1];
    float dn = g_dinv[node];
    const float2* xw2 = (const float2*)g_xw;
    float2 acc = make_float2(0.f, 0.f);
    int s_next = (start < end) ? g_csr[start] : 0;
    for (int e = start; e < end; e++) {
        int s = s_next;
        if (e + 1 < end) s_next = g_csr[e + 1];
        float w = g_dinv[s] * dn;
        float2 v = xw2[s * 32 + lane];
        acc.x += w * v.x; acc.y += w * v.y;
    }
    float2 b = ((const float2*)b_gcn)[lane];
    float2 o;
    o.x = fmaxf(acc.x + b.x, 0.f);
    o.y = fmaxf(acc.y + b.y, 0.f);
    ((float2*)g_h1)[node * 32 + lane] = o;
    g_h1h[node * 32 + lane] = __floats2half2_rn(o.x, o.y);

    const float2* ws2 = (const float2*)g_ws;
    const float2* wd2 = (const float2*)g_wd;
    float p[8];
#pragma unroll
    for (int h = 0; h < 4; h++) {
        float2 ws = ws2[h * 32 + lane];
        float2 wd = wd2[h * 32 + lane];
        p[h]     = o.x * ws.x + o.y * ws.y;
        p[4 + h] = o.x * wd.x + o.y * wd.y;
    }
#pragma unroll
    for (int off = 16; off; off >>= 1) {
#pragma unroll
        for (int j = 0; j < 8; j++) p[j] += __shfl_xor_sync(0xffffffffu, p[j], off);
    }
    if (lane == 0) {
        ((float4*)g_as)[node] = make_float4(p[0], p[1], p[2], p[3]);
        ((float4*)g_ad)[node] = make_float4(p[4], p[5], p[6], p[7]);
    }
}

// ---------------- GAT pass 1: per-node per-head max ----------------
__global__ void gat_max_kernel(int n) {
    int node = (blockIdx.x * blockDim.x + threadIdx.x) >> 5;
    int lane = threadIdx.x & 31;
    if (node >= n) return;
    int start = g_row_ptr[node], end = g_row_ptr[node + 1];
    const float4* as4 = (const float4*)g_as;
    float4 ad = ((const float4*)g_ad)[node];
    float m0 = -1e30f, m1 = -1e30f, m2 = -1e30f, m3 = -1e30f;
    for (int e = start + lane; e < end; e += 32) {
        int s = g_csr[e];
        float4 a = as4[s];
        m0 = fmaxf(m0, lrelu(a.x + ad.x));
        m1 = fmaxf(m1, lrelu(a.y + ad.y));
        m2 = fmaxf(m2, lrelu(a.z + ad.z));
        m3 = fmaxf(m3, lrelu(a.w + ad.w));
    }
#pragma unroll
    for (int off = 16; off; off >>= 1) {
        m0 = fmaxf(m0, __shfl_xor_sync(0xffffffffu, m0, off));
        m1 = fmaxf(m1, __shfl_xor_sync(0xffffffffu, m1, off));
        m2 = fmaxf(m2, __shfl_xor_sync(0xffffffffu, m2, off));
        m3 = fmaxf(m3, __shfl_xor_sync(0xffffffffu, m3, off));
    }
    if (lane == 0) ((float4*)g_m)[node] = make_float4(m0, m1, m2, m3);
}

// ---------------- GAT pass 2: edge-parallel exp weights ----------------
__global__ void gat_exp_kernel(int total) {
    int p = blockIdx.x * blockDim.x + threadIdx.x;
    if (p >= total) return;
    int s = g_csr[p];
    int d = g_pdst[p];
    float4 a  = ((const float4*)g_as)[s];
    float4 ad = ((const float4*)g_ad)[d];
    float4 m  = ((const float4*)g_m)[d];
    half4 out;
    out.a = __floats2half2_rn(__expf(lrelu(a.x + ad.x) - m.x),
                              __expf(lrelu(a.y + ad.y) - m.y));
    out.b = __floats2half2_rn(__expf(lrelu(a.z + ad.z) - m.z),
                              __expf(lrelu(a.w + ad.w) - m.w));
    g_ex[p] = out;
}

// ---------------- GAT pass 3: aggregate h1 (fp16) per head, normalize ----------------
__global__ void gat_agg_kernel(int n) {
    int node = (blockIdx.x * blockDim.x + threadIdx.x) >> 5;
    int lane = threadIdx.x & 31;
    if (node >= n) return;
    int start = g_row_ptr[node], end = g_row_ptr[node + 1];
    float acc[8];
#pragma unroll
    for (int i = 0; i < 8; i++) acc[i] = 0.f;
    float d0 = 0.f, d1 = 0.f, d2 = 0.f, d3 = 0.f;
    int s_cur = (start < end) ? g_csr[start] : 0;
    half4 ex_cur = (start < end) ? g_ex[start]
                 : half4{__floats2half2_rn(0.f, 0.f), __floats2half2_rn(0.f, 0.f)};
    for (int e = start; e < end; e++) {
        int s = s_cur;
        half4 exv = ex_cur;
        if (e + 1 < end) { s_cur = g_csr[e + 1]; ex_cur = g_ex[e + 1]; }
        float2 e01 = __half22float2(exv.a);
        float2 e23 = __half22float2(exv.b);
        d0 += e01.x; d1 += e01.y; d2 += e23.x; d3 += e23.y;
        float2 hv = __half22float2(g_h1h[s * 32 + lane]);
        acc[0] += e01.x * hv.x; acc[1] += e01.x * hv.y;
        acc[2] += e01.y * hv.x; acc[3] += e01.y * hv.y;
        acc[4] += e23.x * hv.x; acc[5] += e23.x * hv.y;
        acc[6] += e23.y * hv.x; acc[7] += e23.y * hv.y;
    }
    float r0 = 1.f / d0, r1 = 1.f / d1, r2 = 1.f / d2, r3 = 1.f / d3;
    float2* u2 = (float2*)g_u;
    u2[node * 128 +       lane] = make_float2(acc[0] * r0, acc[1] * r0);
    u2[node * 128 +  32 + lane] = make_float2(acc[2] * r1, acc[3] * r1);
    u2[node * 128 +  64 + lane] = make_float2(acc[4] * r2, acc[5] * r2);
    u2[node * 128 +  96 + lane] = make_float2(acc[6] * r3, acc[7] * r3);
}

// ---------------- GEMM2b: h2 = relu(0.25 * u @ Wstack + b_gat) ----------------
__global__ void gemm2b_kernel(const float* __restrict__ Wg, const float* __restrict__ b_gat, int n) {
    __shared__ float Wc[HID * HID];
    __shared__ float us[128 * HID];
    int tid = threadIdx.x, q = tid & 15, rg = tid >> 4;
    int rowbase = blockIdx.x * 128;
    u64 accXY[8], accZW[8];
#pragma unroll
    for (int j = 0; j < 8; j++) { accXY[j] = 0ull; accZW[j] = 0ull; }
    const float4* Wg4 = (const float4*)Wg;
    const float4* u4 = (const float4*)g_u;
    float4* Wc4s = (float4*)Wc;
    float4* us4 = (float4*)us;
    const float4* Wc4 = (const float4*)Wc;
    for (int h = 0; h < 4; h++) {
        __syncthreads();
        for (int i = tid; i < 1024; i += 256) {
            int k = i >> 4, j = i & 15;
            Wc4s[i] = Wg4[k * 64 + h * 16 + j];
        }
        for (int i = tid; i < 2048; i += 256) {
            int r = i >> 4, j = i & 15;
            int row = rowbase + r;
            us4[i] = (row < n) ? u4[row * 64 + h * 16 + j] : make_float4(0.f, 0.f, 0.f, 0.f);
        }
        __syncthreads();
#pragma unroll 4
        for (int k = 0; k < HID; k++) {
            float4 w = Wc4[k * 16 + q];
            u64 wxy = pack2(w.x, w.y), wzw = pack2(w.z, w.w);
#pragma unroll
            for (int j = 0; j < 8; j++) {
                float hv = us[(rg * 8 + j) * HID + k];
                u64 hv2 = pack2(hv, hv);
                ffma2(accXY[j], hv2, wxy);
                ffma2(accZW[j], hv2, wzw);
            }
        }
    }
    float4 b = ((const float4*)b_gat)[q];
    float4* h2_4 = (float4*)g_h2;
#pragma unroll
    for (int j = 0; j < 8; j++) {
        int row = rowbase + rg * 8 + j;
        if (row < n) {
            float2 lo = unpack2(accXY[j]), hi = unpack2(accZW[j]);
            float4 o;
            o.x = fmaxf(0.25f * lo.x + b.x, 0.f);
            o.y = fmaxf(0.25f * lo.y + b.y, 0.f);
            o.z = fmaxf(0.25f * hi.x + b.z, 0.f);
            o.w = fmaxf(0.25f * hi.y + b.w, 0.f);
            h2_4[row * 16 + q] = o;
        }
    }
}

// ---------------- patch GEMM (concurrent with GAT chain): hp = h1 @ Wp + bp ----------------
__global__ void patch_kernel(const float* __restrict__ Wp, const float* __restrict__ b_patch, int n) {
    __shared__ float Ws[HID * HID];
    __shared__ float hs[128 * HID];
    int tid = threadIdx.x, q = tid & 15, rg = tid >> 4;
    for (int i = tid; i < HID * HID; i += 256) Ws[i] = Wp[i];
    int rowbase = blockIdx.x * 128;
    const float4* h1_4 = (const float4*)g_h1;
    float4* hs4 = (float4*)hs;
    for (int l = tid; l < 2048; l += 256) {
        int r = l >> 4, c4 = l & 15;
        int row = rowbase + r;
        hs4[l] = (row < n) ? h1_4[row * 16 + c4] : make_float4(0.f, 0.f, 0.f, 0.f);
    }
    __syncthreads();
    u64 accXY[8], accZW[8];
#pragma unroll
    for (int j = 0; j < 8; j++) { accXY[j] = 0ull; accZW[j] = 0ull; }
    const float4* Ws4 = (const float4*)Ws;
#pragma unroll 4
    for (int k = 0; k < HID; k++) {
        float4 w = Ws4[k * 16 + q];
        u64 wxy = pack2(w.x, w.y), wzw = pack2(w.z, w.w);
#pragma unroll
        for (int j = 0; j < 8; j++) {
            float hv = hs[(rg * 8 + j) * HID + k];
            u64 hv2 = pack2(hv, hv);
            ffma2(accXY[j], hv2, wxy);
            ffma2(accZW[j], hv2, wzw);
        }
    }
    float4 bp = ((const float4*)b_patch)[q];
    float4* hp4 = (float4*)g_hp;
#pragma unroll
    for (int j = 0; j < 8; j++) {
        int row = rowbase + rg * 8 + j;
        if (row < n) {
            float2 lo = unpack2(accXY[j]), hi = unpack2(accZW[j]);
            hp4[row * 16 + q] = make_float4(lo.x + bp.x, lo.y + bp.y, hi.x + bp.z, hi.y + bp.w);
        }
    }
}

// ---------------- final LN: h = h1 + h2 + hp; LayerNorm ----------------
__global__ void final_ln_kernel(const float* __restrict__ gamma, const float* __restrict__ beta,
                                float* __restrict__ out, int n) {
    int tid = threadIdx.x, q = tid & 15;
    int row = blockIdx.x * 16 + (tid >> 4);
    if (row >= n) return;
    float4 a = ((const float4*)g_h1)[row * 16 + q];
    float4 b = ((const float4*)g_h2)[row * 16 + q];
    float4 c = ((const float4*)g_hp)[row * 16 + q];
    float4 h;
    h.x = a.x + b.x + c.x;
    h.y = a.y + b.y + c.y;
    h.z = a.z + b.z + c.z;
    h.w = a.w + b.w + c.w;
    float s  = h.x + h.y + h.z + h.w;
    float sq = h.x * h.x + h.y * h.y + h.z * h.z + h.w * h.w;
#pragma unroll
    for (int off = 8; off; off >>= 1) {
        s  += __shfl_xor_sync(0xffffffffu, s, off);
        sq += __shfl_xor_sync(0xffffffffu, sq, off);
    }
    float mu = s * (1.f / 64.f);
    float var = sq * (1.f / 64.f) - mu * mu;
    float rstd = rsqrtf(var + 1e-5f);
    float4 g4  = ((const float4*)gamma)[q];
    float4 bt4 = ((const float4*)beta)[q];
    float4 o;
    o.x = (h.x - mu) * rstd * g4.x + bt4.x;
    o.y = (h.y - mu) * rstd * g4.y + bt4.y;
    o.z = (h.z - mu) * rstd * g4.z + bt4.z;
    o.w = (h.w - mu) * rstd * g4.w + bt4.w;
    ((float4*)out)[row * 16 + q] = o;
}

// ---------------- launch (forked-capture: gemm1 and patch run on side stream) ----------------
extern "C" void kernel_launch(void* const* d_in, const int* in_sizes, int n_in,
                              void* d_out, int out_size) {
    const float* x        = (const float*)d_in[0];
    const void*  ei       = d_in[1];
    const float* W_gcn    = (const float*)d_in[2];
    const float* b_gcn    = (const float*)d_in[3];
    const float* W_gat    = (const float*)d_in[4];
    const float* att_src  = (const float*)d_in[5];
    const float* att_dst  = (const float*)d_in[6];
    const float* b_gat    = (const float*)d_in[7];
    const float* W_patch  = (const float*)d_in[8];
    const float* b_patch  = (const float*)d_in[9];
    const float* gamma    = (const float*)d_in[10];
    const float* beta     = (const float*)d_in[11];
    float* out = (float*)d_out;

    int n = in_sizes[0] / INDIM;          // 50000
    int E = in_sizes[1] / 2;              // 400000

    // one-time host-side resource setup (runs during correctness call, pre-capture)
    static cudaStream_t s2 = nullptr;
    static cudaEvent_t evFork = nullptr, evG = nullptr, evH1 = nullptr, evJoin = nullptr;
    if (s2 == nullptr) {
        cudaStreamCreateWithFlags(&s2, cudaStreamNonBlocking);
        cudaEventCreateWithFlags(&evFork, cudaEventDisableTiming);
        cudaEventCreateWithFlags(&evG,    cudaEventDisableTiming);
        cudaEventCreateWithFlags(&evH1,   cudaEventDisableTiming);
        cudaEventCreateWithFlags(&evJoin, cudaEventDisableTiming);
    }

    const int T = 256;
    int gN   = (n + T - 1) / T;
    int gE   = (E + T - 1) / T;
    int gEN  = (E + n + T - 1) / T;
    int nb   = (n + 255) / 256;
    int g128 = (n + 127) / 128;
    int gLN  = (n + 15) / 16;
    int gWpN = (n * 32 + T - 1) / T;
    (void)nb;

    // fork side stream
    cudaEventRecord(evFork, 0);
    cudaStreamWaitEvent(s2, evFork, 0);
    gemm1_kernel<<<g128, T, 0, s2>>>(x, W_gcn, n);    // independent of graph build
    cudaEventRecord(evG, s2);

    // main chain: graph build
    prep_kernel<<<1, 256>>>((const int*)ei, W_gat, att_src, att_dst);
    hist_kernel<<<gE, T>>>(ei, E);
    scanA_kernel<<<gN, 256>>>(n);
    scanC_kernel<<<gN, 256>>>(n, E + n);
    fill_csr_kernel<<<gEN, T>>>(ei, E, n);

    cudaStreamWaitEvent(0, evG, 0);
    gcn_agg_kernel<<<gWpN, T>>>(b_gcn, n);
    cudaEventRecord(evH1, 0);

    // side stream: patch GEMM concurrent with GAT chain
    cudaStreamWaitEvent(s2, evH1, 0);
    patch_kernel<<<g128, T, 0, s2>>>(W_patch, b_patch, n);
    cudaEventRecord(evJoin, s2);

    gat_max_kernel<<<gWpN, T>>>(n);
    gat_exp_kernel<<<gEN, T>>>(E + n);
    gat_agg_kernel<<<gWpN, T>>>(n);
    gemm2b_kernel<<<g128, T>>>(W_gat, b_gat, n);

    cudaStreamWaitEvent(0, evJoin, 0);
    final_ln_kernel<<<gLN, T>>>(gamma, beta, out, n);
}